// round 6
// baseline (speedup 1.0000x reference)
#include <cuda_runtime.h>
#include <cuda_bf16.h>
#include <math.h>

#define B 64
#define S 20
#define H 128
#define E 300
#define V 50257
#define VP 50304   // V padded to multiple of 128

// ---------------- device scratch (static, no runtime alloc) ----------------
__device__ float g_h0[B * H];
__device__ float g_h1[B * H];
__device__ float g_attn[B * H];
__device__ float g_mem[B * S * H];
__device__ float g_keys[B * S * H];
__device__ float g_na[B * S * H];        // decoder attention outputs (GEMM A)
__device__ float g_Wpad[128 * VP];       // padded W_proj

__device__ __forceinline__ float sigmoidf_(float x) { return 1.f / (1.f + expf(-x)); }

// ---------------- init ----------------
__global__ void init_states_kernel() {
    int i = blockIdx.x * blockDim.x + threadIdx.x;
    if (i < B * H) { g_h0[i] = 0.f; g_h1[i] = 0.f; g_attn[i] = 0.f; }
}

// ---------------- pad W_proj into aligned buffer ----------------
__global__ void padW_kernel(const float* __restrict__ Wp) {
    int c = blockIdx.x * blockDim.x + threadIdx.x;
    int k = blockIdx.y;
    if (c >= VP) return;
    g_Wpad[k * VP + c] = (c < V) ? Wp[(long)k * V + c] : 0.f;
}

// ---------------- encoder step (naive): one block per batch element ----------------
__global__ __launch_bounds__(256) void enc_step_naive(
    const int* __restrict__ x, const float* __restrict__ emb,
    const float* __restrict__ e0_gk, const float* __restrict__ e0_gb,
    const float* __restrict__ e0_ck, const float* __restrict__ e0_cb,
    const float* __restrict__ e1_gk, const float* __restrict__ e1_gb,
    const float* __restrict__ e1_ck, const float* __restrict__ e1_cb,
    const int* __restrict__ x_len, int t)
{
    int b = blockIdx.x;
    int tid = threadIdx.x;

    __shared__ float xe[E];
    __shared__ float h0s[H], h1s[H], n0s[H], n1s[H];
    __shared__ float g0[2 * H], g1[2 * H];

    int id = x[b * S + t];
    for (int e = tid; e < E; e += 256) xe[e] = emb[(long)id * E + e];
    if (tid < H) {
        h0s[tid] = g_h0[b * H + tid];
        h1s[tid] = g_h1[b * H + tid];
    }
    __syncthreads();

    // ---- layer 0 gates: sigmoid([x, h0] @ e0_gk + e0_gb) ----
    {
        int j = tid;
        float acc = e0_gb[j];
        for (int k = 0; k < E; k++) acc += xe[k] * e0_gk[k * 256 + j];
        for (int k = 0; k < H; k++) acc += h0s[k] * e0_gk[(E + k) * 256 + j];
        g0[j] = sigmoidf_(acc);
    }
    __syncthreads();
    // ---- layer 0 candidate: tanh([x, r*h0] @ e0_ck + e0_cb) ----
    if (tid < H) {
        int j = tid;
        float acc = e0_cb[j];
        for (int k = 0; k < E; k++) acc += xe[k] * e0_ck[k * H + j];
        for (int k = 0; k < H; k++) acc += (g0[k] * h0s[k]) * e0_ck[(E + k) * H + j];
        float c = tanhf(acc);
        float u = g0[H + j];
        n0s[j] = u * h0s[j] + (1.f - u) * c;
    }
    __syncthreads();
    // ---- layer 1 gates: sigmoid([n0, h1] @ e1_gk + e1_gb) ----
    {
        int j = tid;
        float acc = e1_gb[j];
        for (int k = 0; k < H; k++) acc += n0s[k] * e1_gk[k * 256 + j];
        for (int k = 0; k < H; k++) acc += h1s[k] * e1_gk[(H + k) * 256 + j];
        g1[j] = sigmoidf_(acc);
    }
    __syncthreads();
    // ---- layer 1 candidate ----
    if (tid < H) {
        int j = tid;
        float acc = e1_cb[j];
        for (int k = 0; k < H; k++) acc += n0s[k] * e1_ck[k * H + j];
        for (int k = 0; k < H; k++) acc += (g1[k] * h1s[k]) * e1_ck[(H + k) * H + j];
        float c = tanhf(acc);
        float u = g1[H + j];
        n1s[j] = u * h1s[j] + (1.f - u) * c;
    }
    __syncthreads();
    // ---- state update + memory output (copy-through masking) ----
    if (tid < H) {
        int j = tid;
        bool valid = (t < x_len[b]);
        if (valid) {
            g_h0[b * H + j] = n0s[j];
            g_h1[b * H + j] = n1s[j];
            g_mem[(b * S + t) * H + j] = n1s[j];
        } else {
            g_mem[(b * S + t) * H + j] = 0.f;
        }
    }
}

// ---------------- keys = memory @ W_mem (naive) ----------------
__global__ __launch_bounds__(128) void keys_naive(const float* __restrict__ W_mem) {
    int row = blockIdx.x;          // 0 .. B*S-1
    int j = threadIdx.x;           // 0 .. H-1
    float acc = 0.f;
    for (int k = 0; k < H; k++) acc += g_mem[row * H + k] * W_mem[k * H + j];
    g_keys[row * H + j] = acc;
}

// ---------------- decoder step (naive): one block per batch element ----------------
__global__ __launch_bounds__(256) void dec_step_naive(
    const int* __restrict__ y, const float* __restrict__ emb,
    const float* __restrict__ d0_gk, const float* __restrict__ d0_gb,
    const float* __restrict__ d0_ck, const float* __restrict__ d0_cb,
    const float* __restrict__ d1_gk, const float* __restrict__ d1_gb,
    const float* __restrict__ d1_ck, const float* __restrict__ d1_cb,
    const float* __restrict__ W_q, const float* __restrict__ v_att,
    const float* __restrict__ W_attn, const int* __restrict__ x_len, int t)
{
    int b = blockIdx.x;
    int tid = threadIdx.x;

    __shared__ float ye[E];
    __shared__ float h0s[H], h1s[H], ats[H], n0s[H], n1s[H], qs[H], ctxs[H];
    __shared__ float g0[2 * H], g1[2 * H];
    __shared__ float sco[S];

    int id = y[b * S + t];
    for (int e = tid; e < E; e += 256) ye[e] = emb[(long)id * E + e];
    if (tid < H) {
        h0s[tid] = g_h0[b * H + tid];
        h1s[tid] = g_h1[b * H + tid];
        ats[tid] = g_attn[b * H + tid];
    }
    __syncthreads();

    // ---- layer 0 gates: sigmoid([y, attn, h0] @ d0_gk + d0_gb) ----
    {
        int j = tid;
        float acc = d0_gb[j];
        for (int k = 0; k < E; k++) acc += ye[k] * d0_gk[k * 256 + j];
        for (int k = 0; k < H; k++) acc += ats[k] * d0_gk[(E + k) * 256 + j];
        for (int k = 0; k < H; k++) acc += h0s[k] * d0_gk[(E + H + k) * 256 + j];
        g0[j] = sigmoidf_(acc);
    }
    __syncthreads();
    // ---- layer 0 candidate: tanh([y, attn, r*h0] @ d0_ck + d0_cb) ----
    if (tid < H) {
        int j = tid;
        float acc = d0_cb[j];
        for (int k = 0; k < E; k++) acc += ye[k] * d0_ck[k * H + j];
        for (int k = 0; k < H; k++) acc += ats[k] * d0_ck[(E + k) * H + j];
        for (int k = 0; k < H; k++) acc += (g0[k] * h0s[k]) * d0_ck[(E + H + k) * H + j];
        float c = tanhf(acc);
        float u = g0[H + j];
        n0s[j] = u * h0s[j] + (1.f - u) * c;
    }
    __syncthreads();
    // ---- layer 1 gates ----
    {
        int j = tid;
        float acc = d1_gb[j];
        for (int k = 0; k < H; k++) acc += n0s[k] * d1_gk[k * 256 + j];
        for (int k = 0; k < H; k++) acc += h1s[k] * d1_gk[(H + k) * 256 + j];
        g1[j] = sigmoidf_(acc);
    }
    __syncthreads();
    // ---- layer 1 candidate ----
    if (tid < H) {
        int j = tid;
        float acc = d1_cb[j];
        for (int k = 0; k < H; k++) acc += n0s[k] * d1_ck[k * H + j];
        for (int k = 0; k < H; k++) acc += (g1[k] * h1s[k]) * d1_ck[(H + k) * H + j];
        float c = tanhf(acc);
        float u = g1[H + j];
        n1s[j] = u * h1s[j] + (1.f - u) * c;
    }
    __syncthreads();
    // ---- query = n1 @ W_q ----
    if (tid < H) {
        int j = tid;
        float acc = 0.f;
        for (int k = 0; k < H; k++) acc += n1s[k] * W_q[k * H + j];
        qs[j] = acc;
    }
    __syncthreads();
    // ---- scores: one thread per source position ----
    if (tid < S) {
        int s = tid;
        float acc = 0.f;
        for (int u = 0; u < H; u++)
            acc += tanhf(g_keys[(b * S + s) * H + u] + qs[u]) * v_att[u];
        if (s >= x_len[b]) acc = -3.4028235e38f;
        sco[s] = acc;
    }
    __syncthreads();
    // ---- softmax (serial, tiny) ----
    if (tid == 0) {
        float m = -3.4028235e38f;
        for (int s = 0; s < S; s++) m = fmaxf(m, sco[s]);
        float sum = 0.f;
        for (int s = 0; s < S; s++) { float ev = expf(sco[s] - m); sco[s] = ev; sum += ev; }
        float inv = 1.f / sum;
        for (int s = 0; s < S; s++) sco[s] *= inv;
    }
    __syncthreads();
    // ---- context ----
    if (tid < H) {
        int j = tid;
        float acc = 0.f;
        for (int s = 0; s < S; s++) acc += sco[s] * g_mem[(b * S + s) * H + j];
        ctxs[j] = acc;
    }
    __syncthreads();
    // ---- na = [n1, ctx] @ W_attn ----
    if (tid < H) {
        int j = tid;
        float acc = 0.f;
        for (int k = 0; k < H; k++) acc += n1s[k] * W_attn[k * H + j];
        for (int k = 0; k < H; k++) acc += ctxs[k] * W_attn[(H + k) * H + j];
        // state updates (all at the end; decoder states are unmasked)
        g_attn[b * H + j] = acc;
        g_na[(b * S + t) * H + j] = acc;
        g_h0[b * H + j] = n0s[j];
        g_h1[b * H + j] = n1s[j];
    }
}

// ---------------- projection GEMM (unchanged from R5; verified clean) ----------------
__global__ __launch_bounds__(256) void proj_kernel(
    const float* __restrict__ bias, const int* __restrict__ y_len,
    float* __restrict__ out)
{
    __shared__ float As[64][129];   // [row][k]
    int bm0 = blockIdx.y * 64;
    int bn0 = blockIdx.x * 128;
    int tid = threadIdx.x;

    for (int e = tid; e < 64 * 128; e += 256) {
        int r = e >> 7, k = e & 127;
        As[r][k] = g_na[(bm0 + r) * H + k];
    }
    __syncthreads();

    int tx = tid & 31;
    int ty = tid >> 5;
    int c0 = bn0 + tx * 4;

    float acc[8][4];
    #pragma unroll
    for (int r = 0; r < 8; r++)
        #pragma unroll
        for (int c = 0; c < 4; c++) acc[r][c] = 0.f;

    const float4* W4 = reinterpret_cast<const float4*>(g_Wpad);
    int wb = c0 >> 2;

    #pragma unroll 2
    for (int k = 0; k < 128; k++) {
        float4 w = W4[k * (VP / 4) + wb];
        #pragma unroll
        for (int r = 0; r < 8; r++) {
            float a = As[ty * 8 + r][k];
            acc[r][0] += a * w.x;
            acc[r][1] += a * w.y;
            acc[r][2] += a * w.z;
            acc[r][3] += a * w.w;
        }
    }

    #pragma unroll
    for (int r = 0; r < 8; r++) {
        int row = bm0 + ty * 8 + r;
        int b = row / S, t = row - b * S;
        bool valid = (t < y_len[b]);
        float* o = out + (long)row * V;
        #pragma unroll
        for (int c = 0; c < 4; c++) {
            int cc = c0 + c;
            if (cc < V) o[cc] = valid ? (acc[r][c] + bias[cc]) : 0.f;
        }
    }
}

// ---------------- host launch ----------------
extern "C" void kernel_launch(void* const* d_in, const int* in_sizes, int n_in,
                              void* d_out, int out_size) {
    const int*   x      = (const int*)d_in[0];
    const int*   x_len  = (const int*)d_in[1];
    const int*   y      = (const int*)d_in[2];
    const int*   y_len  = (const int*)d_in[3];
    const float* emb    = (const float*)d_in[4];
    const float* e0_gk  = (const float*)d_in[5];
    const float* e0_gb  = (const float*)d_in[6];
    const float* e0_ck  = (const float*)d_in[7];
    const float* e0_cb  = (const float*)d_in[8];
    const float* e1_gk  = (const float*)d_in[9];
    const float* e1_gb  = (const float*)d_in[10];
    const float* e1_ck  = (const float*)d_in[11];
    const float* e1_cb  = (const float*)d_in[12];
    const float* d0_gk  = (const float*)d_in[13];
    const float* d0_gb  = (const float*)d_in[14];
    const float* d0_ck  = (const float*)d_in[15];
    const float* d0_cb  = (const float*)d_in[16];
    const float* d1_gk  = (const float*)d_in[17];
    const float* d1_gb  = (const float*)d_in[18];
    const float* d1_ck  = (const float*)d_in[19];
    const float* d1_cb  = (const float*)d_in[20];
    const float* W_mem  = (const float*)d_in[21];
    const float* W_q    = (const float*)d_in[22];
    const float* v_att  = (const float*)d_in[23];
    const float* W_attn = (const float*)d_in[24];
    const float* W_proj = (const float*)d_in[25];
    const float* b_proj = (const float*)d_in[26];
    float* out = (float*)d_out;

    init_states_kernel<<<32, 256>>>();
    padW_kernel<<<dim3((VP + 255) / 256, 128), 256>>>(W_proj);

    for (int t = 0; t < S; t++)
        enc_step_naive<<<B, 256>>>(x, emb,
                                   e0_gk, e0_gb, e0_ck, e0_cb,
                                   e1_gk, e1_gb, e1_ck, e1_cb, x_len, t);

    keys_naive<<<B * S, 128>>>(W_mem);

    for (int t = 0; t < S; t++)
        dec_step_naive<<<B, 256>>>(y, emb,
                                   d0_gk, d0_gb, d0_ck, d0_cb,
                                   d1_gk, d1_gb, d1_ck, d1_cb,
                                   W_q, v_att, W_attn, x_len, t);

    proj_kernel<<<dim3(VP / 128, (B * S) / 64), 256>>>(b_proj, y_len, out);
}

// round 8
// speedup vs baseline: 1.1041x; 1.1041x over previous
#include <cuda_runtime.h>
#include <cuda_bf16.h>
#include <math.h>

#define B 64
#define S 20
#define H 128
#define E 300
#define V 50257
#define VP 50304   // V padded to multiple of 128

// ---------------- device scratch (static, no runtime alloc) ----------------
__device__ float g_h0[B * H];
__device__ float g_h1[B * H];
__device__ float g_mem[B * S * H];
__device__ float g_keys[B * S * H];
__device__ float g_egx[B * S * 2 * H];   // encoder L0 gates x-part (+bias)
__device__ float g_ecx[B * S * H];       // encoder L0 cand  x-part (+bias)
__device__ float g_dgx[B * S * 2 * H];   // decoder L0 gates y-part (+bias)
__device__ float g_dcx[B * S * H];       // decoder L0 cand  y-part (+bias)
__device__ float g_na[B * S * H];        // decoder attention outputs (GEMM A)
__device__ float g_Wpad[128 * VP];       // padded W_proj

__device__ __forceinline__ float sigmoidf_(float x) { return 1.f / (1.f + expf(-x)); }

// ---------------- pad W_proj into aligned buffer ----------------
__global__ void padW_kernel(const float* __restrict__ Wp) {
    int c = blockIdx.x * blockDim.x + threadIdx.x;
    int k = blockIdx.y;
    if (c >= VP) return;
    g_Wpad[k * VP + c] = (c < V) ? Wp[(long)k * V + c] : 0.f;
}

// ---------------- x-part precompute ----------------
// out[row, j] = bias[j] + sum_{k<E} emb[ids[row], k] * W[k*ncols + j]
// 8 rows per block; block = ncols threads (256 for gates, 128 for candidates).
// NOTE: output buffer selected DEVICE-SIDE via `which` — passing a __device__
// symbol as a host-side kernel argument passes the host shadow address, and on
// GB300 (ATS, pageableMemoryAccess=1) the resulting write is SILENTLY wrong.
__global__ void xpart8_kernel(
    const int* __restrict__ ids, const float* __restrict__ emb,
    const float* __restrict__ W, const float* __restrict__ bias,
    int which, int ncols)
{
    float* out = (which == 0) ? g_egx :
                 (which == 1) ? g_ecx :
                 (which == 2) ? g_dgx : g_dcx;

    __shared__ float xs[8][E];
    int row0 = blockIdx.x * 8;
    int tid = threadIdx.x;
    int nt = blockDim.x;

    for (int e = tid; e < 8 * E; e += nt) {
        int r = e / E, k = e - r * E;
        xs[r][k] = emb[(long)ids[row0 + r] * E + k];
    }
    __syncthreads();

    int j = tid;  // one column per thread
    float acc[8];
    #pragma unroll
    for (int r = 0; r < 8; r++) acc[r] = 0.f;
    for (int k = 0; k < E; k++) {
        float w = W[k * ncols + j];
        #pragma unroll
        for (int r = 0; r < 8; r++) acc[r] += xs[r][k] * w;
    }
    float bv = bias[j];
    #pragma unroll
    for (int r = 0; r < 8; r++) out[(row0 + r) * ncols + j] = acc[r] + bv;
}

// ---------------- fused encoder: one block per batch element, t-loop inside ----------------
__global__ __launch_bounds__(256) void enc_fused(
    const float* __restrict__ e0_gk, const float* __restrict__ e0_ck,
    const float* __restrict__ e1_gk, const float* __restrict__ e1_gb,
    const float* __restrict__ e1_ck, const float* __restrict__ e1_cb,
    const int* __restrict__ x_len)
{
    int b = blockIdx.x;
    int tid = threadIdx.x;
    int xlen = x_len[b];

    __shared__ float h0s[H], h1s[H], n0s[H], n1s[H];
    __shared__ float g0[2 * H], g1[2 * H], rh[H];

    if (tid < H) { h0s[tid] = 0.f; h1s[tid] = 0.f; }
    __syncthreads();

    for (int t = 0; t < S; t++) {
        bool valid = (t < xlen);
        // ---- L0 gates: sigmoid(x_part + h0 @ Wg_h) ----
        {
            int j = tid;
            float acc = g_egx[(b * S + t) * 256 + j];
            float a0 = 0.f, a1 = 0.f, a2 = 0.f, a3 = 0.f;
            #pragma unroll 4
            for (int k = 0; k < H; k += 4) {
                a0 += h0s[k]     * e0_gk[(E + k) * 256 + j];
                a1 += h0s[k + 1] * e0_gk[(E + k + 1) * 256 + j];
                a2 += h0s[k + 2] * e0_gk[(E + k + 2) * 256 + j];
                a3 += h0s[k + 3] * e0_gk[(E + k + 3) * 256 + j];
            }
            g0[j] = sigmoidf_(acc + (a0 + a1) + (a2 + a3));
        }
        __syncthreads();
        if (tid < H) rh[tid] = g0[tid] * h0s[tid];
        __syncthreads();
        // ---- L0 candidate ----
        if (tid < H) {
            int j = tid;
            float acc = g_ecx[(b * S + t) * H + j];
            float a0 = 0.f, a1 = 0.f, a2 = 0.f, a3 = 0.f;
            #pragma unroll 4
            for (int k = 0; k < H; k += 4) {
                a0 += rh[k]     * e0_ck[(E + k) * H + j];
                a1 += rh[k + 1] * e0_ck[(E + k + 1) * H + j];
                a2 += rh[k + 2] * e0_ck[(E + k + 2) * H + j];
                a3 += rh[k + 3] * e0_ck[(E + k + 3) * H + j];
            }
            float c = tanhf(acc + (a0 + a1) + (a2 + a3));
            float u = g0[H + j];
            n0s[j] = u * h0s[j] + (1.f - u) * c;
        }
        __syncthreads();
        // ---- L1 gates ----
        {
            int j = tid;
            float acc = e1_gb[j];
            float a0 = 0.f, a1 = 0.f, a2 = 0.f, a3 = 0.f;
            #pragma unroll 4
            for (int k = 0; k < H; k += 4) {
                a0 += n0s[k]     * e1_gk[k * 256 + j];
                a1 += n0s[k + 1] * e1_gk[(k + 1) * 256 + j];
                a2 += n0s[k + 2] * e1_gk[(k + 2) * 256 + j];
                a3 += n0s[k + 3] * e1_gk[(k + 3) * 256 + j];
            }
            #pragma unroll 4
            for (int k = 0; k < H; k += 4) {
                a0 += h1s[k]     * e1_gk[(H + k) * 256 + j];
                a1 += h1s[k + 1] * e1_gk[(H + k + 1) * 256 + j];
                a2 += h1s[k + 2] * e1_gk[(H + k + 2) * 256 + j];
                a3 += h1s[k + 3] * e1_gk[(H + k + 3) * 256 + j];
            }
            g1[j] = sigmoidf_(acc + (a0 + a1) + (a2 + a3));
        }
        __syncthreads();
        if (tid < H) rh[tid] = g1[tid] * h1s[tid];
        __syncthreads();
        // ---- L1 candidate ----
        if (tid < H) {
            int j = tid;
            float acc = e1_cb[j];
            float a0 = 0.f, a1 = 0.f, a2 = 0.f, a3 = 0.f;
            #pragma unroll 4
            for (int k = 0; k < H; k += 4) {
                a0 += n0s[k]     * e1_ck[k * H + j];
                a1 += n0s[k + 1] * e1_ck[(k + 1) * H + j];
                a2 += n0s[k + 2] * e1_ck[(k + 2) * H + j];
                a3 += n0s[k + 3] * e1_ck[(k + 3) * H + j];
            }
            #pragma unroll 4
            for (int k = 0; k < H; k += 4) {
                a0 += rh[k]     * e1_ck[(H + k) * H + j];
                a1 += rh[k + 1] * e1_ck[(H + k + 1) * H + j];
                a2 += rh[k + 2] * e1_ck[(H + k + 2) * H + j];
                a3 += rh[k + 3] * e1_ck[(H + k + 3) * H + j];
            }
            float c = tanhf(acc + (a0 + a1) + (a2 + a3));
            float u = g1[H + j];
            n1s[j] = u * h1s[j] + (1.f - u) * c;
        }
        __syncthreads();
        // ---- state update (copy-through) + memory output ----
        if (tid < H) {
            int j = tid;
            if (valid) {
                h0s[j] = n0s[j];
                h1s[j] = n1s[j];
                g_mem[(b * S + t) * H + j] = n1s[j];
            } else {
                g_mem[(b * S + t) * H + j] = 0.f;
            }
        }
        __syncthreads();
    }
    // final states for decoder
    if (tid < H) {
        g_h0[b * H + tid] = h0s[tid];
        g_h1[b * H + tid] = h1s[tid];
    }
}

// ---------------- keys = memory @ W_mem ----------------
__global__ __launch_bounds__(128) void keys_naive(const float* __restrict__ W_mem) {
    int row = blockIdx.x;          // 0 .. B*S-1
    int j = threadIdx.x;           // 0 .. H-1
    float a0 = 0.f, a1 = 0.f, a2 = 0.f, a3 = 0.f;
    #pragma unroll 4
    for (int k = 0; k < H; k += 4) {
        a0 += g_mem[row * H + k]     * W_mem[k * H + j];
        a1 += g_mem[row * H + k + 1] * W_mem[(k + 1) * H + j];
        a2 += g_mem[row * H + k + 2] * W_mem[(k + 2) * H + j];
        a3 += g_mem[row * H + k + 3] * W_mem[(k + 3) * H + j];
    }
    g_keys[row * H + j] = (a0 + a1) + (a2 + a3);
}

// ---------------- fused decoder: one block per batch element ----------------
__global__ __launch_bounds__(256) void dec_fused(
    const float* __restrict__ d0_gk, const float* __restrict__ d0_ck,
    const float* __restrict__ d1_gk, const float* __restrict__ d1_gb,
    const float* __restrict__ d1_ck, const float* __restrict__ d1_cb,
    const float* __restrict__ W_q, const float* __restrict__ v_att,
    const float* __restrict__ W_attn, const int* __restrict__ x_len)
{
    int b = blockIdx.x;
    int tid = threadIdx.x;
    int xlen = x_len[b];

    __shared__ float h0s[H], h1s[H], ats[H], n0s[H], n1s[H], qs[H], ctxs[H];
    __shared__ float g0[2 * H], g1[2 * H], rh[H];
    __shared__ float part[S][8], sco[S];

    if (tid < H) {
        h0s[tid] = g_h0[b * H + tid];
        h1s[tid] = g_h1[b * H + tid];
        ats[tid] = 0.f;
    }
    __syncthreads();

    for (int t = 0; t < S; t++) {
        // ---- L0 gates: sigmoid(y_part + [attn, h0] @ Wg_h) ----
        {
            int j = tid;
            float acc = g_dgx[(b * S + t) * 256 + j];
            float a0 = 0.f, a1 = 0.f, a2 = 0.f, a3 = 0.f;
            #pragma unroll 4
            for (int k = 0; k < H; k += 4) {
                a0 += ats[k]     * d0_gk[(E + k) * 256 + j];
                a1 += ats[k + 1] * d0_gk[(E + k + 1) * 256 + j];
                a2 += ats[k + 2] * d0_gk[(E + k + 2) * 256 + j];
                a3 += ats[k + 3] * d0_gk[(E + k + 3) * 256 + j];
            }
            #pragma unroll 4
            for (int k = 0; k < H; k += 4) {
                a0 += h0s[k]     * d0_gk[(E + H + k) * 256 + j];
                a1 += h0s[k + 1] * d0_gk[(E + H + k + 1) * 256 + j];
                a2 += h0s[k + 2] * d0_gk[(E + H + k + 2) * 256 + j];
                a3 += h0s[k + 3] * d0_gk[(E + H + k + 3) * 256 + j];
            }
            g0[j] = sigmoidf_(acc + (a0 + a1) + (a2 + a3));
        }
        __syncthreads();
        if (tid < H) rh[tid] = g0[tid] * h0s[tid];
        __syncthreads();
        // ---- L0 candidate ----
        if (tid < H) {
            int j = tid;
            float acc = g_dcx[(b * S + t) * H + j];
            float a0 = 0.f, a1 = 0.f, a2 = 0.f, a3 = 0.f;
            #pragma unroll 4
            for (int k = 0; k < H; k += 4) {
                a0 += ats[k]     * d0_ck[(E + k) * H + j];
                a1 += ats[k + 1] * d0_ck[(E + k + 1) * H + j];
                a2 += ats[k + 2] * d0_ck[(E + k + 2) * H + j];
                a3 += ats[k + 3] * d0_ck[(E + k + 3) * H + j];
            }
            #pragma unroll 4
            for (int k = 0; k < H; k += 4) {
                a0 += rh[k]     * d0_ck[(E + H + k) * H + j];
                a1 += rh[k + 1] * d0_ck[(E + H + k + 1) * H + j];
                a2 += rh[k + 2] * d0_ck[(E + H + k + 2) * H + j];
                a3 += rh[k + 3] * d0_ck[(E + H + k + 3) * H + j];
            }
            float c = tanhf(acc + (a0 + a1) + (a2 + a3));
            float u = g0[H + j];
            n0s[j] = u * h0s[j] + (1.f - u) * c;
        }
        __syncthreads();
        // ---- L1 gates ----
        {
            int j = tid;
            float acc = d1_gb[j];
            float a0 = 0.f, a1 = 0.f, a2 = 0.f, a3 = 0.f;
            #pragma unroll 4
            for (int k = 0; k < H; k += 4) {
                a0 += n0s[k]     * d1_gk[k * 256 + j];
                a1 += n0s[k + 1] * d1_gk[(k + 1) * 256 + j];
                a2 += n0s[k + 2] * d1_gk[(k + 2) * 256 + j];
                a3 += n0s[k + 3] * d1_gk[(k + 3) * 256 + j];
            }
            #pragma unroll 4
            for (int k = 0; k < H; k += 4) {
                a0 += h1s[k]     * d1_gk[(H + k) * 256 + j];
                a1 += h1s[k + 1] * d1_gk[(H + k + 1) * 256 + j];
                a2 += h1s[k + 2] * d1_gk[(H + k + 2) * 256 + j];
                a3 += h1s[k + 3] * d1_gk[(H + k + 3) * 256 + j];
            }
            g1[j] = sigmoidf_(acc + (a0 + a1) + (a2 + a3));
        }
        __syncthreads();
        if (tid < H) rh[tid] = g1[tid] * h1s[tid];
        __syncthreads();
        // ---- L1 candidate ----
        if (tid < H) {
            int j = tid;
            float acc = d1_cb[j];
            float a0 = 0.f, a1 = 0.f, a2 = 0.f, a3 = 0.f;
            #pragma unroll 4
            for (int k = 0; k < H; k += 4) {
                a0 += n0s[k]     * d1_ck[k * H + j];
                a1 += n0s[k + 1] * d1_ck[(k + 1) * H + j];
                a2 += n0s[k + 2] * d1_ck[(k + 2) * H + j];
                a3 += n0s[k + 3] * d1_ck[(k + 3) * H + j];
            }
            #pragma unroll 4
            for (int k = 0; k < H; k += 4) {
                a0 += rh[k]     * d1_ck[(H + k) * H + j];
                a1 += rh[k + 1] * d1_ck[(H + k + 1) * H + j];
                a2 += rh[k + 2] * d1_ck[(H + k + 2) * H + j];
                a3 += rh[k + 3] * d1_ck[(H + k + 3) * H + j];
            }
            float c = tanhf(acc + (a0 + a1) + (a2 + a3));
            float u = g1[H + j];
            n1s[j] = u * h1s[j] + (1.f - u) * c;
        }
        __syncthreads();
        // ---- query = n1 @ W_q ----
        if (tid < H) {
            int j = tid;
            float a0 = 0.f, a1 = 0.f, a2 = 0.f, a3 = 0.f;
            #pragma unroll 4
            for (int k = 0; k < H; k += 4) {
                a0 += n1s[k]     * W_q[k * H + j];
                a1 += n1s[k + 1] * W_q[(k + 1) * H + j];
                a2 += n1s[k + 2] * W_q[(k + 2) * H + j];
                a3 += n1s[k + 3] * W_q[(k + 3) * H + j];
            }
            qs[j] = (a0 + a1) + (a2 + a3);
        }
        __syncthreads();
        // ---- attention score partials: (s, l) split, 16 elems each ----
        if (tid < 8 * S) {
            int s = tid >> 3, l = tid & 7;
            float acc = 0.f;
            const float* kr = &g_keys[(b * S + s) * H + l * 16];
            const float* qr = &qs[l * 16];
            const float* vr = &v_att[l * 16];
            #pragma unroll
            for (int u = 0; u < 16; u++) acc += tanhf(kr[u] + qr[u]) * vr[u];
            part[s][l] = acc;
        }
        __syncthreads();
        if (tid < S) {
            float sc = 0.f;
            #pragma unroll
            for (int l = 0; l < 8; l++) sc += part[tid][l];
            if (tid >= xlen) sc = -3.4028235e38f;
            sco[tid] = sc;
        }
        __syncthreads();
        // ---- softmax (serial, tiny) ----
        if (tid == 0) {
            float m = -3.4028235e38f;
            for (int s = 0; s < S; s++) m = fmaxf(m, sco[s]);
            float sum = 0.f;
            for (int s = 0; s < S; s++) { float ev = expf(sco[s] - m); sco[s] = ev; sum += ev; }
            float inv = 1.f / sum;
            for (int s = 0; s < S; s++) sco[s] *= inv;
        }
        __syncthreads();
        // ---- context ----
        if (tid < H) {
            int j = tid;
            float acc = 0.f;
            #pragma unroll
            for (int s = 0; s < S; s++) acc += sco[s] * g_mem[(b * S + s) * H + j];
            ctxs[j] = acc;
        }
        __syncthreads();
        // ---- na = [n1, ctx] @ W_attn; update all carries ----
        if (tid < H) {
            int j = tid;
            float a0 = 0.f, a1 = 0.f, a2 = 0.f, a3 = 0.f;
            #pragma unroll 4
            for (int k = 0; k < H; k += 4) {
                a0 += n1s[k]     * W_attn[k * H + j];
                a1 += n1s[k + 1] * W_attn[(k + 1) * H + j];
                a2 += n1s[k + 2] * W_attn[(k + 2) * H + j];
                a3 += n1s[k + 3] * W_attn[(k + 3) * H + j];
            }
            #pragma unroll 4
            for (int k = 0; k < H; k += 4) {
                a0 += ctxs[k]     * W_attn[(H + k) * H + j];
                a1 += ctxs[k + 1] * W_attn[(H + k + 1) * H + j];
                a2 += ctxs[k + 2] * W_attn[(H + k + 2) * H + j];
                a3 += ctxs[k + 3] * W_attn[(H + k + 3) * H + j];
            }
            float na = (a0 + a1) + (a2 + a3);
            ats[j] = na;
            g_na[(b * S + t) * H + j] = na;
            h0s[j] = n0s[j];
            h1s[j] = n1s[j];
        }
        __syncthreads();
    }
}

// ---------------- projection GEMM: f32x2 packed FFMA (2x fp32 MAC rate) ----------------
__device__ __forceinline__ void ffma2(unsigned long long& d, unsigned long long a, unsigned long long b) {
    asm("fma.rn.f32x2 %0, %1, %2, %0;" : "+l"(d) : "l"(a), "l"(b));
}
__device__ __forceinline__ unsigned long long dup2(float x) {
    unsigned long long r;
    asm("mov.b64 %0, {%1, %1};" : "=l"(r) : "r"(__float_as_uint(x)));
    return r;
}

#define PROJ_SMEM ((128 * 129 + 128 * 128) * 4)

__global__ __launch_bounds__(256, 1) void proj_kernel(
    const float* __restrict__ bias, const int* __restrict__ y_len,
    float* __restrict__ out)
{
    extern __shared__ float sm[];
    float* As = sm;                                                   // [128][129]
    unsigned long long* As2 = (unsigned long long*)(sm + 128 * 129);  // [k][64] row-pairs

    int bm0 = blockIdx.y * 128;
    int bn0 = blockIdx.x * 128;
    int tid = threadIdx.x;

    // stage 1: coalesced load of A tile (128 rows x 128 k)
    for (int e = tid; e < 128 * 128; e += 256) {
        int r = e >> 7, k = e & 127;
        As[r * 129 + k] = g_na[(bm0 + r) * H + k];
    }
    __syncthreads();
    // stage 2: repack into row-pair float2 [k][pair]
    for (int e = tid; e < 128 * 64; e += 256) {
        int p = e & 63, k = e >> 6;
        float2 v = make_float2(As[(2 * p) * 129 + k], As[(2 * p + 1) * 129 + k]);
        As2[k * 64 + p] = *reinterpret_cast<unsigned long long*>(&v);
    }
    __syncthreads();

    int tx = tid & 31, wid = tid >> 5;
    int p0 = wid * 8;                 // 8 row-pairs = rows wid*16 .. wid*16+15
    int c0 = bn0 + tx * 4;            // 4 consecutive cols

    unsigned long long acc[8][4];
    #pragma unroll
    for (int p = 0; p < 8; p++)
        #pragma unroll
        for (int c = 0; c < 4; c++) acc[p][c] = 0ull;

    const float4* W4 = reinterpret_cast<const float4*>(g_Wpad);
    int wbase = (c0 >> 2);

    #pragma unroll 4
    for (int k = 0; k < 128; k++) {
        float4 w = W4[k * (VP / 4) + wbase];
        unsigned long long wd0 = dup2(w.x), wd1 = dup2(w.y), wd2 = dup2(w.z), wd3 = dup2(w.w);
        const unsigned long long* a2 = &As2[k * 64 + p0];
        #pragma unroll
        for (int p = 0; p < 8; p++) {
            unsigned long long av = a2[p];
            ffma2(acc[p][0], av, wd0);
            ffma2(acc[p][1], av, wd1);
            ffma2(acc[p][2], av, wd2);
            ffma2(acc[p][3], av, wd3);
        }
    }

    // epilogue: write every row; zero rows past y_length
    #pragma unroll
    for (int p = 0; p < 8; p++) {
        int r0 = wid * 16 + 2 * p;
        #pragma unroll
        for (int half = 0; half < 2; half++) {
            int rr = r0 + half;
            int row = bm0 + rr;
            int b = row / S, t = row - b * S;
            bool valid = (t < y_len[b]);
            float* o = out + (long)row * V;
            #pragma unroll
            for (int c = 0; c < 4; c++) {
                int cc = c0 + c;
                if (cc < V) {
                    unsigned long long a = acc[p][c];
                    unsigned int bits = half ? (unsigned int)(a >> 32) : (unsigned int)(a & 0xffffffffull);
                    o[cc] = valid ? (__uint_as_float(bits) + bias[cc]) : 0.f;
                }
            }
        }
    }
}

// ---------------- host launch ----------------
extern "C" void kernel_launch(void* const* d_in, const int* in_sizes, int n_in,
                              void* d_out, int out_size) {
    const int*   x      = (const int*)d_in[0];
    const int*   x_len  = (const int*)d_in[1];
    const int*   y      = (const int*)d_in[2];
    const int*   y_len  = (const int*)d_in[3];
    const float* emb    = (const float*)d_in[4];
    const float* e0_gk  = (const float*)d_in[5];
    const float* e0_gb  = (const float*)d_in[6];
    const float* e0_ck  = (const float*)d_in[7];
    const float* e0_cb  = (const float*)d_in[8];
    const float* e1_gk  = (const float*)d_in[9];
    const float* e1_gb  = (const float*)d_in[10];
    const float* e1_ck  = (const float*)d_in[11];
    const float* e1_cb  = (const float*)d_in[12];
    const float* d0_gk  = (const float*)d_in[13];
    const float* d0_gb  = (const float*)d_in[14];
    const float* d0_ck  = (const float*)d_in[15];
    const float* d0_cb  = (const float*)d_in[16];
    const float* d1_gk  = (const float*)d_in[17];
    const float* d1_gb  = (const float*)d_in[18];
    const float* d1_ck  = (const float*)d_in[19];
    const float* d1_cb  = (const float*)d_in[20];
    const float* W_mem  = (const float*)d_in[21];
    const float* W_q    = (const float*)d_in[22];
    const float* v_att  = (const float*)d_in[23];
    const float* W_attn = (const float*)d_in[24];
    const float* W_proj = (const float*)d_in[25];
    const float* b_proj = (const float*)d_in[26];
    float* out = (float*)d_out;

    cudaFuncSetAttribute(proj_kernel, cudaFuncAttributeMaxDynamicSharedMemorySize, PROJ_SMEM);

    padW_kernel<<<dim3((VP + 255) / 256, 128), 256>>>(W_proj);

    // x-part precompute (embedding gather fused); output selected device-side
    xpart8_kernel<<<(B * S) / 8, 256>>>(x, emb, e0_gk, e0_gb, 0, 256);
    xpart8_kernel<<<(B * S) / 8, 128>>>(x, emb, e0_ck, e0_cb, 1, 128);
    xpart8_kernel<<<(B * S) / 8, 256>>>(y, emb, d0_gk, d0_gb, 2, 256);
    xpart8_kernel<<<(B * S) / 8, 128>>>(y, emb, d0_ck, d0_cb, 3, 128);

    enc_fused<<<B, 256>>>(e0_gk, e0_ck, e1_gk, e1_gb, e1_ck, e1_cb, x_len);

    keys_naive<<<B * S, 128>>>(W_mem);

    dec_fused<<<B, 256>>>(d0_gk, d0_ck, d1_gk, d1_gb, d1_ck, d1_cb,
                          W_q, v_att, W_attn, x_len);

    proj_kernel<<<dim3(VP / 128, (B * S) / 128), 256, PROJ_SMEM>>>(b_proj, y_len, out);
}

// round 9
// speedup vs baseline: 1.9690x; 1.7834x over previous
#include <cuda_runtime.h>
#include <cuda_bf16.h>
#include <math.h>

#define B 64
#define S 20
#define H 128
#define E 300
#define V 50257
#define VP 50304   // V padded to multiple of 128

// ---------------- device scratch (static, no runtime alloc) ----------------
__device__ float g_h0[B * H];
__device__ float g_h1[B * H];
__device__ float g_mem[B * S * H];
__device__ float g_keys[B * S * H];
__device__ float g_egx[B * S * 2 * H];   // encoder L0 gates x-part (+bias)
__device__ float g_ecx[B * S * H];       // encoder L0 cand  x-part (+bias)
__device__ float g_dgx[B * S * 2 * H];   // decoder L0 gates y-part (+bias)
__device__ float g_dcx[B * S * H];       // decoder L0 cand  y-part (+bias)
__device__ float g_na[B * S * H];        // decoder attention outputs (GEMM A)
__device__ float g_Wpad[128 * VP];       // padded W_proj

__device__ __forceinline__ float sigmoidf_(float x) { return 1.f / (1.f + expf(-x)); }

// partial-sum helper: serial chain of `n` weight loads, 4 accumulators
__device__ __forceinline__ float dotchunk(const float* __restrict__ src,
                                          const float* __restrict__ W, int ldw, int n) {
    float a0 = 0.f, a1 = 0.f, a2 = 0.f, a3 = 0.f;
    #pragma unroll 8
    for (int k = 0; k < n; k += 4) {
        a0 += src[k]     * W[k * ldw];
        a1 += src[k + 1] * W[(k + 1) * ldw];
        a2 += src[k + 2] * W[(k + 2) * ldw];
        a3 += src[k + 3] * W[(k + 3) * ldw];
    }
    return (a0 + a1) + (a2 + a3);
}

// ---------------- pad W_proj into aligned buffer ----------------
__global__ void padW_kernel(const float* __restrict__ Wp) {
    int c = blockIdx.x * blockDim.x + threadIdx.x;
    int k = blockIdx.y;
    if (c >= VP) return;
    g_Wpad[k * VP + c] = (c < V) ? Wp[(long)k * V + c] : 0.f;
}

// ---------------- x-part precompute ----------------
// out[row, j] = bias[j] + sum_{k<E} emb[ids[row], k] * W[k*ncols + j]
// output selected DEVICE-SIDE (host-side __device__ symbol args are silently
// wrong on GB300 due to ATS).
__global__ void xpart8_kernel(
    const int* __restrict__ ids, const float* __restrict__ emb,
    const float* __restrict__ W, const float* __restrict__ bias,
    int which, int ncols)
{
    float* out = (which == 0) ? g_egx :
                 (which == 1) ? g_ecx :
                 (which == 2) ? g_dgx : g_dcx;

    __shared__ float xs[8][E];
    int row0 = blockIdx.x * 8;
    int tid = threadIdx.x;
    int nt = blockDim.x;

    for (int e = tid; e < 8 * E; e += nt) {
        int r = e / E, k = e - r * E;
        xs[r][k] = emb[(long)ids[row0 + r] * E + k];
    }
    __syncthreads();

    int j = tid;
    float acc[8];
    #pragma unroll
    for (int r = 0; r < 8; r++) acc[r] = 0.f;
    #pragma unroll 10
    for (int k = 0; k < E; k++) {
        float w = W[k * ncols + j];
        #pragma unroll
        for (int r = 0; r < 8; r++) acc[r] += xs[r][k] * w;
    }
    float bv = bias[j];
    #pragma unroll
    for (int r = 0; r < 8; r++) out[(row0 + r) * ncols + j] = acc[r] + bv;
}

// ---------------- fused encoder: 1024 threads per batch element ----------------
__global__ __launch_bounds__(1024, 1) void enc_fused(
    const float* __restrict__ e0_gk, const float* __restrict__ e0_ck,
    const float* __restrict__ e1_gk, const float* __restrict__ e1_gb,
    const float* __restrict__ e1_ck, const float* __restrict__ e1_cb,
    const int* __restrict__ x_len)
{
    int b = blockIdx.x;
    int tid = threadIdx.x;
    int xlen = x_len[b];

    __shared__ float h0s[H], h1s[H], n0s[H], rh[H];
    __shared__ float us0[H], us1[H];
    __shared__ float pp[1024];

    if (tid < H) { h0s[tid] = 0.f; h1s[tid] = 0.f; }
    __syncthreads();

    for (int t = 0; t < S; t++) {
        // ---- Phase A: L0 gates partials (256 cols x 4 k-chunks of 32, h0 part) ----
        {
            int j = tid & 255, kq = tid >> 8;
            pp[kq * 256 + j] = dotchunk(h0s + kq * 32, e0_gk + (E + kq * 32) * 256 + j, 256, 32);
        }
        __syncthreads();
        if (tid < 256) {
            float acc = g_egx[(b * S + t) * 256 + tid]
                      + pp[tid] + pp[256 + tid] + pp[512 + tid] + pp[768 + tid];
            float v = sigmoidf_(acc);
            if (tid < H) rh[tid] = v * h0s[tid];
            else us0[tid - H] = v;
        }
        __syncthreads();
        // ---- Phase B: L0 candidate partials (128 cols x 8 chunks of 16, rh part) ----
        {
            int j = tid & 127, kq = tid >> 7;
            pp[kq * 128 + j] = dotchunk(rh + kq * 16, e0_ck + (E + kq * 16) * H + j, H, 16);
        }
        __syncthreads();
        if (tid < H) {
            float acc = g_ecx[(b * S + t) * H + tid];
            #pragma unroll
            for (int q = 0; q < 8; q++) acc += pp[q * 128 + tid];
            float c = tanhf(acc);
            float u = us0[tid];
            n0s[tid] = u * h0s[tid] + (1.f - u) * c;
        }
        __syncthreads();
        // ---- Phase C: L1 gates (256 cols x 4 chunks of 64 over concat [n0, h1]) ----
        {
            int j = tid & 255, kq = tid >> 8;
            const float* src = (kq < 2) ? (n0s + kq * 64) : (h1s + (kq - 2) * 64);
            pp[kq * 256 + j] = dotchunk(src, e1_gk + (kq * 64) * 256 + j, 256, 64);
        }
        __syncthreads();
        if (tid < 256) {
            float acc = e1_gb[tid]
                      + pp[tid] + pp[256 + tid] + pp[512 + tid] + pp[768 + tid];
            float v = sigmoidf_(acc);
            if (tid < H) rh[tid] = v * h1s[tid];
            else us1[tid - H] = v;
        }
        __syncthreads();
        // ---- Phase D: L1 candidate (128 cols x 8 chunks of 32 over [n0, rh]) ----
        {
            int j = tid & 127, kq = tid >> 7;
            const float* src = (kq < 4) ? (n0s + kq * 32) : (rh + (kq - 4) * 32);
            pp[kq * 128 + j] = dotchunk(src, e1_ck + (kq * 32) * H + j, H, 32);
        }
        __syncthreads();
        if (tid < H) {
            float acc = e1_cb[tid];
            #pragma unroll
            for (int q = 0; q < 8; q++) acc += pp[q * 128 + tid];
            float c = tanhf(acc);
            float u = us1[tid];
            float n1 = u * h1s[tid] + (1.f - u) * c;
            if (t < xlen) {
                h0s[tid] = n0s[tid];
                h1s[tid] = n1;
                g_mem[(b * S + t) * H + tid] = n1;
            } else {
                g_mem[(b * S + t) * H + tid] = 0.f;
            }
        }
        __syncthreads();
    }
    if (tid < H) {
        g_h0[b * H + tid] = h0s[tid];
        g_h1[b * H + tid] = h1s[tid];
    }
}

// ---------------- keys = memory @ W_mem ----------------
__global__ __launch_bounds__(128) void keys_naive(const float* __restrict__ W_mem) {
    int row = blockIdx.x;
    int j = threadIdx.x;
    float a0 = 0.f, a1 = 0.f, a2 = 0.f, a3 = 0.f;
    #pragma unroll 8
    for (int k = 0; k < H; k += 4) {
        a0 += g_mem[row * H + k]     * W_mem[k * H + j];
        a1 += g_mem[row * H + k + 1] * W_mem[(k + 1) * H + j];
        a2 += g_mem[row * H + k + 2] * W_mem[(k + 2) * H + j];
        a3 += g_mem[row * H + k + 3] * W_mem[(k + 3) * H + j];
    }
    g_keys[row * H + j] = (a0 + a1) + (a2 + a3);
}

// ---------------- fused decoder: 1024 threads per batch element ----------------
__global__ __launch_bounds__(1024, 1) void dec_fused(
    const float* __restrict__ d0_gk, const float* __restrict__ d0_ck,
    const float* __restrict__ d1_gk, const float* __restrict__ d1_gb,
    const float* __restrict__ d1_ck, const float* __restrict__ d1_cb,
    const float* __restrict__ W_q, const float* __restrict__ v_att,
    const float* __restrict__ W_attn, const int* __restrict__ x_len)
{
    int b = blockIdx.x;
    int tid = threadIdx.x;
    int lid = tid & 31;
    int wid = tid >> 5;
    int xlen = x_len[b];

    __shared__ float h0s[H], h1s[H], ats[H], n0s[H], n1s[H], qs[H], ctxs[H], rh[H];
    __shared__ float us0[H], us1[H];
    __shared__ float pp[1024];
    __shared__ float sco[S];

    if (tid < H) {
        h0s[tid] = g_h0[b * H + tid];
        h1s[tid] = g_h1[b * H + tid];
        ats[tid] = 0.f;
    }
    __syncthreads();

    for (int t = 0; t < S; t++) {
        // ---- Phase A: L0 gates (256 cols x 4 chunks of 64 over concat [attn, h0]) ----
        {
            int j = tid & 255, kq = tid >> 8;
            const float* src = (kq < 2) ? (ats + kq * 64) : (h0s + (kq - 2) * 64);
            pp[kq * 256 + j] = dotchunk(src, d0_gk + (E + kq * 64) * 256 + j, 256, 64);
        }
        __syncthreads();
        if (tid < 256) {
            float acc = g_dgx[(b * S + t) * 256 + tid]
                      + pp[tid] + pp[256 + tid] + pp[512 + tid] + pp[768 + tid];
            float v = sigmoidf_(acc);
            if (tid < H) rh[tid] = v * h0s[tid];
            else us0[tid - H] = v;
        }
        __syncthreads();
        // ---- Phase B: L0 candidate (128 cols x 8 chunks of 32 over [attn, rh]) ----
        {
            int j = tid & 127, kq = tid >> 7;
            const float* src = (kq < 4) ? (ats + kq * 32) : (rh + (kq - 4) * 32);
            pp[kq * 128 + j] = dotchunk(src, d0_ck + (E + kq * 32) * H + j, H, 32);
        }
        __syncthreads();
        if (tid < H) {
            float acc = g_dcx[(b * S + t) * H + tid];
            #pragma unroll
            for (int q = 0; q < 8; q++) acc += pp[q * 128 + tid];
            float c = tanhf(acc);
            float u = us0[tid];
            n0s[tid] = u * h0s[tid] + (1.f - u) * c;
        }
        __syncthreads();
        // ---- Phase C: L1 gates (256 cols x 4 chunks of 64 over [n0, h1]) ----
        {
            int j = tid & 255, kq = tid >> 8;
            const float* src = (kq < 2) ? (n0s + kq * 64) : (h1s + (kq - 2) * 64);
            pp[kq * 256 + j] = dotchunk(src, d1_gk + (kq * 64) * 256 + j, 256, 64);
        }
        __syncthreads();
        if (tid < 256) {
            float acc = d1_gb[tid]
                      + pp[tid] + pp[256 + tid] + pp[512 + tid] + pp[768 + tid];
            float v = sigmoidf_(acc);
            if (tid < H) rh[tid] = v * h1s[tid];
            else us1[tid - H] = v;
        }
        __syncthreads();
        // ---- Phase D: L1 candidate (128 cols x 8 chunks of 32 over [n0, rh]) ----
        {
            int j = tid & 127, kq = tid >> 7;
            const float* src = (kq < 4) ? (n0s + kq * 32) : (rh + (kq - 4) * 32);
            pp[kq * 128 + j] = dotchunk(src, d1_ck + (kq * 32) * H + j, H, 32);
        }
        __syncthreads();
        if (tid < H) {
            float acc = d1_cb[tid];
            #pragma unroll
            for (int q = 0; q < 8; q++) acc += pp[q * 128 + tid];
            float c = tanhf(acc);
            float u = us1[tid];
            n1s[tid] = u * h1s[tid] + (1.f - u) * c;
        }
        __syncthreads();
        // ---- query = n1 @ W_q (128 cols x 8 chunks of 16) ----
        {
            int j = tid & 127, kq = tid >> 7;
            pp[kq * 128 + j] = dotchunk(n1s + kq * 16, W_q + (kq * 16) * H + j, H, 16);
        }
        __syncthreads();
        if (tid < H) {
            float acc = 0.f;
            #pragma unroll
            for (int q = 0; q < 8; q++) acc += pp[q * 128 + tid];
            qs[tid] = acc;
        }
        __syncthreads();
        // ---- attention scores: one warp per source position ----
        if (wid < S) {
            int s = wid;
            float acc = 0.f;
            const float* kr = &g_keys[(b * S + s) * H];
            #pragma unroll
            for (int u = 0; u < 4; u++) {
                int uu = lid + u * 32;
                acc += tanhf(kr[uu] + qs[uu]) * v_att[uu];
            }
            #pragma unroll
            for (int off = 16; off > 0; off >>= 1)
                acc += __shfl_xor_sync(0xffffffffu, acc, off);
            if (lid == 0)
                sco[s] = (s >= xlen) ? -3.4028235e38f : acc;
        }
        __syncthreads();
        // ---- softmax (serial, tiny) ----
        if (tid == 0) {
            float m = -3.4028235e38f;
            #pragma unroll
            for (int s = 0; s < S; s++) m = fmaxf(m, sco[s]);
            float sum = 0.f;
            #pragma unroll
            for (int s = 0; s < S; s++) { float ev = expf(sco[s] - m); sco[s] = ev; sum += ev; }
            float inv = 1.f / sum;
            #pragma unroll
            for (int s = 0; s < S; s++) sco[s] *= inv;
        }
        __syncthreads();
        // ---- context ----
        if (tid < H) {
            float acc = 0.f;
            #pragma unroll
            for (int s = 0; s < S; s++) acc += sco[s] * g_mem[(b * S + s) * H + tid];
            ctxs[tid] = acc;
        }
        __syncthreads();
        // ---- na = [n1, ctx] @ W_attn (128 cols x 8 chunks of 32) ----
        {
            int j = tid & 127, kq = tid >> 7;
            const float* src = (kq < 4) ? (n1s + kq * 32) : (ctxs + (kq - 4) * 32);
            pp[kq * 128 + j] = dotchunk(src, W_attn + (kq * 32) * H + j, H, 32);
        }
        __syncthreads();
        if (tid < H) {
            float acc = 0.f;
            #pragma unroll
            for (int q = 0; q < 8; q++) acc += pp[q * 128 + tid];
            ats[tid] = acc;
            g_na[(b * S + t) * H + tid] = acc;
            h0s[tid] = n0s[tid];
            h1s[tid] = n1s[tid];
        }
        __syncthreads();
    }
}

// ---------------- projection GEMM: f32x2 packed FFMA (2x fp32 MAC rate) ----------------
__device__ __forceinline__ void ffma2(unsigned long long& d, unsigned long long a, unsigned long long b) {
    asm("fma.rn.f32x2 %0, %1, %2, %0;" : "+l"(d) : "l"(a), "l"(b));
}
__device__ __forceinline__ unsigned long long dup2(float x) {
    unsigned long long r;
    asm("mov.b64 %0, {%1, %1};" : "=l"(r) : "r"(__float_as_uint(x)));
    return r;
}

#define PROJ_SMEM ((128 * 129 + 128 * 128) * 4)

__global__ __launch_bounds__(256, 1) void proj_kernel(
    const float* __restrict__ bias, const int* __restrict__ y_len,
    float* __restrict__ out)
{
    extern __shared__ float sm[];
    float* As = sm;                                                   // [128][129]
    unsigned long long* As2 = (unsigned long long*)(sm + 128 * 129);  // [k][64] row-pairs

    int bm0 = blockIdx.y * 128;
    int bn0 = blockIdx.x * 128;
    int tid = threadIdx.x;

    for (int e = tid; e < 128 * 128; e += 256) {
        int r = e >> 7, k = e & 127;
        As[r * 129 + k] = g_na[(bm0 + r) * H + k];
    }
    __syncthreads();
    for (int e = tid; e < 128 * 64; e += 256) {
        int p = e & 63, k = e >> 6;
        float2 v = make_float2(As[(2 * p) * 129 + k], As[(2 * p + 1) * 129 + k]);
        As2[k * 64 + p] = *reinterpret_cast<unsigned long long*>(&v);
    }
    __syncthreads();

    int tx = tid & 31, wid = tid >> 5;
    int p0 = wid * 8;
    int c0 = bn0 + tx * 4;

    unsigned long long acc[8][4];
    #pragma unroll
    for (int p = 0; p < 8; p++)
        #pragma unroll
        for (int c = 0; c < 4; c++) acc[p][c] = 0ull;

    const float4* W4 = reinterpret_cast<const float4*>(g_Wpad);
    int wbase = (c0 >> 2);

    #pragma unroll 4
    for (int k = 0; k < 128; k++) {
        float4 w = W4[k * (VP / 4) + wbase];
        unsigned long long wd0 = dup2(w.x), wd1 = dup2(w.y), wd2 = dup2(w.z), wd3 = dup2(w.w);
        const unsigned long long* a2 = &As2[k * 64 + p0];
        #pragma unroll
        for (int p = 0; p < 8; p++) {
            unsigned long long av = a2[p];
            ffma2(acc[p][0], av, wd0);
            ffma2(acc[p][1], av, wd1);
            ffma2(acc[p][2], av, wd2);
            ffma2(acc[p][3], av, wd3);
        }
    }

    #pragma unroll
    for (int p = 0; p < 8; p++) {
        int r0 = wid * 16 + 2 * p;
        #pragma unroll
        for (int half = 0; half < 2; half++) {
            int rr = r0 + half;
            int row = bm0 + rr;
            int b = row / S, t = row - b * S;
            bool valid = (t < y_len[b]);
            float* o = out + (long)row * V;
            #pragma unroll
            for (int c = 0; c < 4; c++) {
                int cc = c0 + c;
                if (cc < V) {
                    unsigned long long a = acc[p][c];
                    unsigned int bits = half ? (unsigned int)(a >> 32) : (unsigned int)(a & 0xffffffffull);
                    o[cc] = valid ? (__uint_as_float(bits) + bias[cc]) : 0.f;
                }
            }
        }
    }
}

// ---------------- host launch ----------------
extern "C" void kernel_launch(void* const* d_in, const int* in_sizes, int n_in,
                              void* d_out, int out_size) {
    const int*   x      = (const int*)d_in[0];
    const int*   x_len  = (const int*)d_in[1];
    const int*   y      = (const int*)d_in[2];
    const int*   y_len  = (const int*)d_in[3];
    const float* emb    = (const float*)d_in[4];
    const float* e0_gk  = (const float*)d_in[5];
    const float* e0_gb  = (const float*)d_in[6];
    const float* e0_ck  = (const float*)d_in[7];
    const float* e0_cb  = (const float*)d_in[8];
    const float* e1_gk  = (const float*)d_in[9];
    const float* e1_gb  = (const float*)d_in[10];
    const float* e1_ck  = (const float*)d_in[11];
    const float* e1_cb  = (const float*)d_in[12];
    const float* d0_gk  = (const float*)d_in[13];
    const float* d0_gb  = (const float*)d_in[14];
    const float* d0_ck  = (const float*)d_in[15];
    const float* d0_cb  = (const float*)d_in[16];
    const float* d1_gk  = (const float*)d_in[17];
    const float* d1_gb  = (const float*)d_in[18];
    const float* d1_ck  = (const float*)d_in[19];
    const float* d1_cb  = (const float*)d_in[20];
    const float* W_mem  = (const float*)d_in[21];
    const float* W_q    = (const float*)d_in[22];
    const float* v_att  = (const float*)d_in[23];
    const float* W_attn = (const float*)d_in[24];
    const float* W_proj = (const float*)d_in[25];
    const float* b_proj = (const float*)d_in[26];
    float* out = (float*)d_out;

    cudaFuncSetAttribute(proj_kernel, cudaFuncAttributeMaxDynamicSharedMemorySize, PROJ_SMEM);

    padW_kernel<<<dim3((VP + 255) / 256, 128), 256>>>(W_proj);

    xpart8_kernel<<<(B * S) / 8, 256>>>(x, emb, e0_gk, e0_gb, 0, 256);
    xpart8_kernel<<<(B * S) / 8, 128>>>(x, emb, e0_ck, e0_cb, 1, 128);
    xpart8_kernel<<<(B * S) / 8, 256>>>(y, emb, d0_gk, d0_gb, 2, 256);
    xpart8_kernel<<<(B * S) / 8, 128>>>(y, emb, d0_ck, d0_cb, 3, 128);

    enc_fused<<<B, 1024>>>(e0_gk, e0_ck, e1_gk, e1_gb, e1_ck, e1_cb, x_len);

    keys_naive<<<B * S, 128>>>(W_mem);

    dec_fused<<<B, 1024>>>(d0_gk, d0_ck, d1_gk, d1_gb, d1_ck, d1_cb,
                           W_q, v_att, W_attn, x_len);

    proj_kernel<<<dim3(VP / 128, (B * S) / 128), 256, PROJ_SMEM>>>(b_proj, y_len, out);
}

// round 10
// speedup vs baseline: 2.1863x; 1.1104x over previous
#include <cuda_runtime.h>
#include <cuda_bf16.h>
#include <math.h>

#define B 64
#define S 20
#define H 128
#define E 300
#define V 50257
#define VP 50304   // V padded to multiple of 128

// ---------------- device scratch (static, no runtime alloc) ----------------
__device__ float g_h0[B * H];
__device__ float g_h1[B * H];
__device__ float g_mem[B * S * H];
__device__ float g_keys[B * S * H];
__device__ float g_egx[B * S * 2 * H];   // encoder L0 gates x-part (+bias)
__device__ float g_ecx[B * S * H];       // encoder L0 cand  x-part (+bias)
__device__ float g_dgx[B * S * 2 * H];   // decoder L0 gates y-part (+bias)
__device__ float g_dcx[B * S * H];       // decoder L0 cand  y-part (+bias)
__device__ float g_na[B * S * H];        // decoder attention outputs (GEMM A)
__device__ float g_Wpad[128 * VP];       // padded W_proj

__device__ __forceinline__ float sigmoidf_(float x) { return 1.f / (1.f + expf(-x)); }

// ---------------- vectorized matvec partials ----------------
// Computes partial sums of src[0..K) @ W[K x NCOLS] into pp (NKQ x NCOLS).
// Thread layout: NCG = NCOLS/4 col-groups (float4 weight loads) x NKQ k-chunks,
// NCG*NKQ == 1024. Chunk of CH = K/NKQ fully unrolled -> CH independent LDG.128.
template<int NCOLS, int K>
__device__ __forceinline__ void mv_partials(
    const float* __restrict__ src, const float* __restrict__ W,
    float* __restrict__ pp, int tid)
{
    constexpr int NCG = NCOLS / 4;
    constexpr int NKQ = 1024 / NCG;
    constexpr int CH  = K / NKQ;
    int cg = tid & (NCG - 1);
    int kq = tid / NCG;
    const float4* Wb = reinterpret_cast<const float4*>(W + (kq * CH) * NCOLS) + cg;
    const float* s = src + kq * CH;
    float4 a = make_float4(0.f, 0.f, 0.f, 0.f);
    #pragma unroll
    for (int k = 0; k < CH; k++) {
        float sv = s[k];
        float4 w = Wb[k * NCG];
        a.x += sv * w.x; a.y += sv * w.y; a.z += sv * w.z; a.w += sv * w.w;
    }
    reinterpret_cast<float4*>(pp)[kq * NCG + cg] = a;   // pp[kq*NCOLS + j]
}

// ---------------- pad W_proj into aligned buffer ----------------
__global__ void padW_kernel(const float* __restrict__ Wp) {
    int c = blockIdx.x * blockDim.x + threadIdx.x;
    int k = blockIdx.y;
    if (c >= VP) return;
    g_Wpad[k * VP + c] = (c < V) ? Wp[(long)k * V + c] : 0.f;
}

// ---------------- x-part precompute (all 4 outputs, one launch) ----------------
// grid (160, 4): blockIdx.y selects {egx, ecx, dgx, dcx}. Output buffer and
// weight selected DEVICE-SIDE (host-side __device__ symbol args are silently
// wrong on GB300 due to ATS).
__global__ void xpart_all_kernel(
    const int* __restrict__ x, const int* __restrict__ y,
    const float* __restrict__ emb,
    const float* __restrict__ e0_gk, const float* __restrict__ e0_gb,
    const float* __restrict__ e0_ck, const float* __restrict__ e0_cb,
    const float* __restrict__ d0_gk, const float* __restrict__ d0_gb,
    const float* __restrict__ d0_ck, const float* __restrict__ d0_cb)
{
    int which = blockIdx.y;
    float* out;
    const float* W; const float* bias; const int* ids; int ncols;
    switch (which) {
        case 0:  out = g_egx; W = e0_gk; bias = e0_gb; ids = x; ncols = 256; break;
        case 1:  out = g_ecx; W = e0_ck; bias = e0_cb; ids = x; ncols = 128; break;
        case 2:  out = g_dgx; W = d0_gk; bias = d0_gb; ids = y; ncols = 256; break;
        default: out = g_dcx; W = d0_ck; bias = d0_cb; ids = y; ncols = 128; break;
    }

    __shared__ float xs[8][E];
    int row0 = blockIdx.x * 8;
    int tid = threadIdx.x;

    for (int e = tid; e < 8 * E; e += 256) {
        int r = e / E, k = e - r * E;
        xs[r][k] = emb[(long)ids[row0 + r] * E + k];
    }
    __syncthreads();

    if (tid < ncols) {
        int j = tid;
        float acc[8];
        #pragma unroll
        for (int r = 0; r < 8; r++) acc[r] = 0.f;
        #pragma unroll 10
        for (int k = 0; k < E; k++) {
            float w = W[k * ncols + j];
            #pragma unroll
            for (int r = 0; r < 8; r++) acc[r] += xs[r][k] * w;
        }
        float bv = bias[j];
        #pragma unroll
        for (int r = 0; r < 8; r++) out[(row0 + r) * ncols + j] = acc[r] + bv;
    }
}

// ---------------- fused encoder: 1024 threads per batch element ----------------
__global__ __launch_bounds__(1024, 1) void enc_fused(
    const float* __restrict__ e0_gk, const float* __restrict__ e0_ck,
    const float* __restrict__ e1_gk, const float* __restrict__ e1_gb,
    const float* __restrict__ e1_ck, const float* __restrict__ e1_cb,
    const int* __restrict__ x_len)
{
    int b = blockIdx.x;
    int tid = threadIdx.x;
    int xlen = x_len[b];

    __shared__ float h0s[H], h1s[H], n0s[H], us0[H], us1[H], rh[H];
    __shared__ float cb[2 * H];
    __shared__ float pp[4096];

    if (tid < H) { h0s[tid] = 0.f; h1s[tid] = 0.f; }
    __syncthreads();

    for (int t = 0; t < S; t++) {
        // ---- A: L0 gates (h0-part), K=128, NCOLS=256 ----
        mv_partials<256, 128>(h0s, e0_gk + E * 256, pp, tid);
        __syncthreads();
        if (tid < 256) {
            float acc = g_egx[(b * S + t) * 256 + tid];
            #pragma unroll
            for (int q = 0; q < 16; q++) acc += pp[q * 256 + tid];
            float v = sigmoidf_(acc);
            if (tid < H) rh[tid] = v * h0s[tid];
            else us0[tid - H] = v;
        }
        __syncthreads();
        // ---- B: L0 candidate (rh-part), K=128, NCOLS=128 ----
        mv_partials<128, 128>(rh, e0_ck + E * 128, pp, tid);
        __syncthreads();
        if (tid < H) {
            float acc = g_ecx[(b * S + t) * H + tid];
            #pragma unroll
            for (int q = 0; q < 32; q++) acc += pp[q * 128 + tid];
            float c = tanhf(acc);
            float u = us0[tid];
            float n0 = u * h0s[tid] + (1.f - u) * c;
            n0s[tid] = n0;
            cb[tid] = n0;           // concat [n0, h1]
            cb[H + tid] = h1s[tid];
        }
        __syncthreads();
        // ---- C: L1 gates over [n0, h1], K=256, NCOLS=256 ----
        mv_partials<256, 256>(cb, e1_gk, pp, tid);
        __syncthreads();
        if (tid < 256) {
            float acc = e1_gb[tid];
            #pragma unroll
            for (int q = 0; q < 16; q++) acc += pp[q * 256 + tid];
            float v = sigmoidf_(acc);
            if (tid < H) cb[H + tid] = v * h1s[tid];   // concat -> [n0, r*h1]
            else us1[tid - H] = v;
        }
        __syncthreads();
        // ---- D: L1 candidate over [n0, r*h1], K=256, NCOLS=128 ----
        mv_partials<128, 256>(cb, e1_ck, pp, tid);
        __syncthreads();
        if (tid < H) {
            float acc = e1_cb[tid];
            #pragma unroll
            for (int q = 0; q < 32; q++) acc += pp[q * 128 + tid];
            float c = tanhf(acc);
            float u = us1[tid];
            float n1 = u * h1s[tid] + (1.f - u) * c;
            if (t < xlen) {
                h0s[tid] = n0s[tid];
                h1s[tid] = n1;
                g_mem[(b * S + t) * H + tid] = n1;
            } else {
                g_mem[(b * S + t) * H + tid] = 0.f;
            }
        }
        __syncthreads();
    }
    if (tid < H) {
        g_h0[b * H + tid] = h0s[tid];
        g_h1[b * H + tid] = h1s[tid];
    }
}

// ---------------- keys = memory @ W_mem ----------------
__global__ __launch_bounds__(128) void keys_naive(const float* __restrict__ W_mem) {
    int row = blockIdx.x;
    int j = threadIdx.x;
    float a0 = 0.f, a1 = 0.f, a2 = 0.f, a3 = 0.f;
    #pragma unroll 8
    for (int k = 0; k < H; k += 4) {
        a0 += g_mem[row * H + k]     * W_mem[k * H + j];
        a1 += g_mem[row * H + k + 1] * W_mem[(k + 1) * H + j];
        a2 += g_mem[row * H + k + 2] * W_mem[(k + 2) * H + j];
        a3 += g_mem[row * H + k + 3] * W_mem[(k + 3) * H + j];
    }
    g_keys[row * H + j] = (a0 + a1) + (a2 + a3);
}

// ---------------- fused decoder: 1024 threads per batch element ----------------
__global__ __launch_bounds__(1024, 1) void dec_fused(
    const float* __restrict__ d0_gk, const float* __restrict__ d0_ck,
    const float* __restrict__ d1_gk, const float* __restrict__ d1_gb,
    const float* __restrict__ d1_ck, const float* __restrict__ d1_cb,
    const float* __restrict__ W_q, const float* __restrict__ v_att,
    const float* __restrict__ W_attn, const int* __restrict__ x_len)
{
    int b = blockIdx.x;
    int tid = threadIdx.x;
    int lid = tid & 31;
    int wid = tid >> 5;
    int xlen = x_len[b];

    __shared__ float h0s[H], h1s[H], n0s[H], n1s[H], qs[H], us0[H], us1[H];
    __shared__ float cb[2 * H];
    __shared__ float pp[4096];
    __shared__ float sco[S];

    if (tid < H) {
        h0s[tid] = g_h0[b * H + tid];
        h1s[tid] = g_h1[b * H + tid];
        cb[tid] = 0.f;               // attn_0 = 0
        cb[H + tid] = h0s[tid];      // concat [attn, h0]
    }
    __syncthreads();

    for (int t = 0; t < S; t++) {
        // ---- A: L0 gates over [attn, h0], K=256, NCOLS=256 ----
        mv_partials<256, 256>(cb, d0_gk + E * 256, pp, tid);
        __syncthreads();
        if (tid < 256) {
            float acc = g_dgx[(b * S + t) * 256 + tid];
            #pragma unroll
            for (int q = 0; q < 16; q++) acc += pp[q * 256 + tid];
            float v = sigmoidf_(acc);
            if (tid < H) cb[H + tid] = v * h0s[tid];   // -> [attn, r*h0]
            else us0[tid - H] = v;
        }
        __syncthreads();
        // ---- B: L0 candidate over [attn, r*h0], K=256, NCOLS=128 ----
        mv_partials<128, 256>(cb, d0_ck + E * 128, pp, tid);
        __syncthreads();
        if (tid < H) {
            float acc = g_dcx[(b * S + t) * H + tid];
            #pragma unroll
            for (int q = 0; q < 32; q++) acc += pp[q * 128 + tid];
            float c = tanhf(acc);
            float u = us0[tid];
            float n0 = u * h0s[tid] + (1.f - u) * c;
            n0s[tid] = n0;
            cb[tid] = n0;            // -> [n0, h1]
            cb[H + tid] = h1s[tid];
        }
        __syncthreads();
        // ---- C: L1 gates over [n0, h1], K=256, NCOLS=256 ----
        mv_partials<256, 256>(cb, d1_gk, pp, tid);
        __syncthreads();
        if (tid < 256) {
            float acc = d1_gb[tid];
            #pragma unroll
            for (int q = 0; q < 16; q++) acc += pp[q * 256 + tid];
            float v = sigmoidf_(acc);
            if (tid < H) cb[H + tid] = v * h1s[tid];   // -> [n0, r*h1]
            else us1[tid - H] = v;
        }
        __syncthreads();
        // ---- D: L1 candidate over [n0, r*h1], K=256, NCOLS=128 ----
        mv_partials<128, 256>(cb, d1_ck, pp, tid);
        __syncthreads();
        if (tid < H) {
            float acc = d1_cb[tid];
            #pragma unroll
            for (int q = 0; q < 32; q++) acc += pp[q * 128 + tid];
            float c = tanhf(acc);
            float u = us1[tid];
            float n1 = u * h1s[tid] + (1.f - u) * c;
            n1s[tid] = n1;
            cb[tid] = n1;            // first half of [n1, ctx]
        }
        __syncthreads();
        // ---- Q: query = n1 @ W_q, K=128, NCOLS=128 ----
        mv_partials<128, 128>(n1s, W_q, pp, tid);
        __syncthreads();
        if (tid < H) {
            float acc = 0.f;
            #pragma unroll
            for (int q = 0; q < 32; q++) acc += pp[q * 128 + tid];
            qs[tid] = acc;
        }
        __syncthreads();
        // ---- attention scores: one warp per source position ----
        if (wid < S) {
            int s = wid;
            float acc = 0.f;
            const float* kr = &g_keys[(b * S + s) * H];
            #pragma unroll
            for (int u = 0; u < 4; u++) {
                int uu = lid + u * 32;
                acc += tanhf(kr[uu] + qs[uu]) * v_att[uu];
            }
            #pragma unroll
            for (int off = 16; off > 0; off >>= 1)
                acc += __shfl_xor_sync(0xffffffffu, acc, off);
            if (lid == 0)
                sco[s] = (s >= xlen) ? -3.4028235e38f : acc;
        }
        __syncthreads();
        // ---- softmax (serial, tiny) ----
        if (tid == 0) {
            float m = -3.4028235e38f;
            #pragma unroll
            for (int s = 0; s < S; s++) m = fmaxf(m, sco[s]);
            float sum = 0.f;
            #pragma unroll
            for (int s = 0; s < S; s++) { float ev = expf(sco[s] - m); sco[s] = ev; sum += ev; }
            float inv = 1.f / sum;
            #pragma unroll
            for (int s = 0; s < S; s++) sco[s] *= inv;
        }
        __syncthreads();
        // ---- context -> second half of [n1, ctx] ----
        if (tid < H) {
            float acc = 0.f;
            #pragma unroll
            for (int s = 0; s < S; s++) acc += sco[s] * g_mem[(b * S + s) * H + tid];
            cb[H + tid] = acc;
        }
        __syncthreads();
        // ---- NA: na = [n1, ctx] @ W_attn, K=256, NCOLS=128 ----
        mv_partials<128, 256>(cb, W_attn, pp, tid);
        __syncthreads();
        if (tid < H) {
            float acc = 0.f;
            #pragma unroll
            for (int q = 0; q < 32; q++) acc += pp[q * 128 + tid];
            g_na[(b * S + t) * H + tid] = acc;
            // carries for next step: cb = [attn, h0new]
            h0s[tid] = n0s[tid];
            h1s[tid] = n1s[tid];
            cb[tid] = acc;
            cb[H + tid] = n0s[tid];
        }
        __syncthreads();
    }
}

// ---------------- projection GEMM: f32x2 packed FFMA (2x fp32 MAC rate) ----------------
__device__ __forceinline__ void ffma2(unsigned long long& d, unsigned long long a, unsigned long long b) {
    asm("fma.rn.f32x2 %0, %1, %2, %0;" : "+l"(d) : "l"(a), "l"(b));
}
__device__ __forceinline__ unsigned long long dup2(float x) {
    unsigned long long r;
    asm("mov.b64 %0, {%1, %1};" : "=l"(r) : "r"(__float_as_uint(x)));
    return r;
}

#define PROJ_SMEM ((128 * 129 + 128 * 128) * 4)

__global__ __launch_bounds__(256, 1) void proj_kernel(
    const float* __restrict__ bias, const int* __restrict__ y_len,
    float* __restrict__ out)
{
    extern __shared__ float sm[];
    float* As = sm;                                                   // [128][129]
    unsigned long long* As2 = (unsigned long long*)(sm + 128 * 129);  // [k][64] row-pairs

    int bm0 = blockIdx.y * 128;
    int bn0 = blockIdx.x * 128;
    int tid = threadIdx.x;

    for (int e = tid; e < 128 * 128; e += 256) {
        int r = e >> 7, k = e & 127;
        As[r * 129 + k] = g_na[(bm0 + r) * H + k];
    }
    __syncthreads();
    for (int e = tid; e < 128 * 64; e += 256) {
        int p = e & 63, k = e >> 6;
        float2 v = make_float2(As[(2 * p) * 129 + k], As[(2 * p + 1) * 129 + k]);
        As2[k * 64 + p] = *reinterpret_cast<unsigned long long*>(&v);
    }
    __syncthreads();

    int tx = tid & 31, wid = tid >> 5;
    int p0 = wid * 8;
    int c0 = bn0 + tx * 4;

    unsigned long long acc[8][4];
    #pragma unroll
    for (int p = 0; p < 8; p++)
        #pragma unroll
        for (int c = 0; c < 4; c++) acc[p][c] = 0ull;

    const float4* W4 = reinterpret_cast<const float4*>(g_Wpad);
    int wbase = (c0 >> 2);

    #pragma unroll 4
    for (int k = 0; k < 128; k++) {
        float4 w = W4[k * (VP / 4) + wbase];
        unsigned long long wd0 = dup2(w.x), wd1 = dup2(w.y), wd2 = dup2(w.z), wd3 = dup2(w.w);
        const unsigned long long* a2 = &As2[k * 64 + p0];
        #pragma unroll
        for (int p = 0; p < 8; p++) {
            unsigned long long av = a2[p];
            ffma2(acc[p][0], av, wd0);
            ffma2(acc[p][1], av, wd1);
            ffma2(acc[p][2], av, wd2);
            ffma2(acc[p][3], av, wd3);
        }
    }

    #pragma unroll
    for (int p = 0; p < 8; p++) {
        int r0 = wid * 16 + 2 * p;
        #pragma unroll
        for (int half = 0; half < 2; half++) {
            int rr = r0 + half;
            int row = bm0 + rr;
            int b = row / S, t = row - b * S;
            bool valid = (t < y_len[b]);
            float* o = out + (long)row * V;
            #pragma unroll
            for (int c = 0; c < 4; c++) {
                int cc = c0 + c;
                if (cc < V) {
                    unsigned long long a = acc[p][c];
                    unsigned int bits = half ? (unsigned int)(a >> 32) : (unsigned int)(a & 0xffffffffull);
                    o[cc] = valid ? (__uint_as_float(bits) + bias[cc]) : 0.f;
                }
            }
        }
    }
}

// ---------------- host launch ----------------
extern "C" void kernel_launch(void* const* d_in, const int* in_sizes, int n_in,
                              void* d_out, int out_size) {
    const int*   x      = (const int*)d_in[0];
    const int*   x_len  = (const int*)d_in[1];
    const int*   y      = (const int*)d_in[2];
    const int*   y_len  = (const int*)d_in[3];
    const float* emb    = (const float*)d_in[4];
    const float* e0_gk  = (const float*)d_in[5];
    const float* e0_gb  = (const float*)d_in[6];
    const float* e0_ck  = (const float*)d_in[7];
    const float* e0_cb  = (const float*)d_in[8];
    const float* e1_gk  = (const float*)d_in[9];
    const float* e1_gb  = (const float*)d_in[10];
    const float* e1_ck  = (const float*)d_in[11];
    const float* e1_cb  = (const float*)d_in[12];
    const float* d0_gk  = (const float*)d_in[13];
    const float* d0_gb  = (const float*)d_in[14];
    const float* d0_ck  = (const float*)d_in[15];
    const float* d0_cb  = (const float*)d_in[16];
    const float* d1_gk  = (const float*)d_in[17];
    const float* d1_gb  = (const float*)d_in[18];
    const float* d1_ck  = (const float*)d_in[19];
    const float* d1_cb  = (const float*)d_in[20];
    const float* W_mem  = (const float*)d_in[21];
    const float* W_q    = (const float*)d_in[22];
    const float* v_att  = (const float*)d_in[23];
    const float* W_attn = (const float*)d_in[24];
    const float* W_proj = (const float*)d_in[25];
    const float* b_proj = (const float*)d_in[26];
    float* out = (float*)d_out;

    cudaFuncSetAttribute(proj_kernel, cudaFuncAttributeMaxDynamicSharedMemorySize, PROJ_SMEM);

    padW_kernel<<<dim3((VP + 255) / 256, 128), 256>>>(W_proj);

    xpart_all_kernel<<<dim3((B * S) / 8, 4), 256>>>(
        x, y, emb, e0_gk, e0_gb, e0_ck, e0_cb, d0_gk, d0_gb, d0_ck, d0_cb);

    enc_fused<<<B, 1024>>>(e0_gk, e0_ck, e1_gk, e1_gb, e1_ck, e1_cb, x_len);

    keys_naive<<<B * S, 128>>>(W_mem);

    dec_fused<<<B, 1024>>>(d0_gk, d0_ck, d1_gk, d1_gb, d1_ck, d1_cb,
                           W_q, v_att, W_attn, x_len);

    proj_kernel<<<dim3(VP / 128, (B * S) / 128), 256, PROJ_SMEM>>>(b_proj, y_len, out);
}

// round 11
// speedup vs baseline: 2.2135x; 1.0125x over previous
#include <cuda_runtime.h>
#include <cuda_bf16.h>
#include <math.h>

#define B 64
#define S 20
#define H 128
#define E 300
#define V 50257
#define VP 50304   // V padded to multiple of 128

// ---------------- device scratch (static, no runtime alloc) ----------------
__device__ float g_h0[B * H];
__device__ float g_h1[B * H];
__device__ float g_mem[B * S * H];
__device__ float g_keys[B * S * H];
__device__ float g_egx[B * S * 2 * H];   // encoder L0 gates x-part (+bias)
__device__ float g_ecx[B * S * H];       // encoder L0 cand  x-part (+bias)
__device__ float g_dgx[B * S * 2 * H];   // decoder L0 gates y-part (+bias)
__device__ float g_dcx[B * S * H];       // decoder L0 cand  y-part (+bias)
__device__ float g_na[B * S * H];        // decoder attention outputs (GEMM A)
__device__ float g_Wpad[128 * VP];       // padded W_proj

__device__ __forceinline__ float sigmoidf_(float x) { return 1.f / (1.f + expf(-x)); }

// ---------------- cluster helpers ----------------
__device__ __forceinline__ unsigned ctarank_() {
    unsigned r; asm("mov.u32 %0, %%cluster_ctarank;" : "=r"(r)); return r;
}
__device__ __forceinline__ void cluster_sync_() {
    asm volatile("barrier.cluster.arrive.aligned;" ::: "memory");
    asm volatile("barrier.cluster.wait.aligned;" ::: "memory");
}
// store a float into the PEER CTA's copy of a shared array element
__device__ __forceinline__ void st_peer(float* p, unsigned peer, float v) {
    unsigned la = (unsigned)__cvta_generic_to_shared(p);
    unsigned ra;
    asm("mapa.shared::cluster.u32 %0, %1, %2;" : "=r"(ra) : "r"(la), "r"(peer));
    asm volatile("st.shared::cluster.f32 [%0], %1;" :: "r"(ra), "f"(v));
}

// ---------------- vectorized matvec partials (column-tile version) ----------------
// Partial sums of src[0..K) @ W[K x (ld LDW)] restricted to NCT columns
// starting at the pointer W (caller pre-offsets to the column base).
// NCG = NCT/4 col-groups (float4 loads) x NKQ k-chunks; NCG*NKQ == 1024.
template<int NCT, int LDW, int K>
__device__ __forceinline__ void mv_t(
    const float* __restrict__ src, const float* __restrict__ W,
    float* __restrict__ pp, int tid)
{
    constexpr int NCG = NCT / 4;
    constexpr int NKQ = 1024 / NCG;
    constexpr int CH  = K / NKQ;
    int cg = tid & (NCG - 1);
    int kq = tid / NCG;
    const float4* Wb = reinterpret_cast<const float4*>(W + (kq * CH) * LDW) + cg;
    const float* s = src + kq * CH;
    float4 a = make_float4(0.f, 0.f, 0.f, 0.f);
    #pragma unroll
    for (int k = 0; k < CH; k++) {
        float sv = s[k];
        float4 w = Wb[k * (LDW / 4)];
        a.x += sv * w.x; a.y += sv * w.y; a.z += sv * w.z; a.w += sv * w.w;
    }
    reinterpret_cast<float4*>(pp)[kq * NCG + cg] = a;   // pp[kq*NCT + j]
}

// ---------------- pad W_proj into aligned buffer ----------------
__global__ void padW_kernel(const float* __restrict__ Wp) {
    int c = blockIdx.x * blockDim.x + threadIdx.x;
    int k = blockIdx.y;
    if (c >= VP) return;
    g_Wpad[k * VP + c] = (c < V) ? Wp[(long)k * V + c] : 0.f;
}

// ---------------- x-part precompute (all 4 outputs, one launch) ----------------
__global__ void xpart_all_kernel(
    const int* __restrict__ x, const int* __restrict__ y,
    const float* __restrict__ emb,
    const float* __restrict__ e0_gk, const float* __restrict__ e0_gb,
    const float* __restrict__ e0_ck, const float* __restrict__ e0_cb,
    const float* __restrict__ d0_gk, const float* __restrict__ d0_gb,
    const float* __restrict__ d0_ck, const float* __restrict__ d0_cb)
{
    int which = blockIdx.y;
    float* out;
    const float* W; const float* bias; const int* ids; int ncols;
    switch (which) {
        case 0:  out = g_egx; W = e0_gk; bias = e0_gb; ids = x; ncols = 256; break;
        case 1:  out = g_ecx; W = e0_ck; bias = e0_cb; ids = x; ncols = 128; break;
        case 2:  out = g_dgx; W = d0_gk; bias = d0_gb; ids = y; ncols = 256; break;
        default: out = g_dcx; W = d0_ck; bias = d0_cb; ids = y; ncols = 128; break;
    }

    __shared__ float xs[8][E];
    int row0 = blockIdx.x * 8;
    int tid = threadIdx.x;

    for (int e = tid; e < 8 * E; e += 256) {
        int r = e / E, k = e - r * E;
        xs[r][k] = emb[(long)ids[row0 + r] * E + k];
    }
    __syncthreads();

    if (tid < ncols) {
        int j = tid;
        float acc[8];
        #pragma unroll
        for (int r = 0; r < 8; r++) acc[r] = 0.f;
        #pragma unroll 10
        for (int k = 0; k < E; k++) {
            float w = W[k * ncols + j];
            #pragma unroll
            for (int r = 0; r < 8; r++) acc[r] += xs[r][k] * w;
        }
        float bv = bias[j];
        #pragma unroll
        for (int r = 0; r < 8; r++) out[(row0 + r) * ncols + j] = acc[r] + bv;
    }
}

// ---------------- fused encoder: 2-CTA cluster per batch element ----------------
__global__ void __cluster_dims__(2, 1, 1) __launch_bounds__(1024, 1) enc_fused(
    const float* __restrict__ e0_gk, const float* __restrict__ e0_ck,
    const float* __restrict__ e1_gk, const float* __restrict__ e1_gb,
    const float* __restrict__ e1_ck, const float* __restrict__ e1_cb,
    const int* __restrict__ x_len)
{
    int b = blockIdx.x >> 1;
    unsigned rank = ctarank_();
    unsigned peer = rank ^ 1u;
    int tid = threadIdx.x;
    int xlen = x_len[b];

    __shared__ float h0s[H], h1s[H], n0s[H], us0[H], us1[H], rh[H];
    __shared__ float cb[2 * H];
    __shared__ float pp[4096];

    if (tid < H) { h0s[tid] = 0.f; h1s[tid] = 0.f; }
    cluster_sync_();

    for (int t = 0; t < S; t++) {
        bool valid = (t < xlen);
        // ---- A: L0 gates (h0-part), cols [rank*128, +128), K=128 ----
        mv_t<128, 256, 128>(h0s, e0_gk + E * 256 + rank * 128, pp, tid);
        __syncthreads();
        if (tid < 128) {
            int gc = rank * 128 + tid;
            float acc = g_egx[(b * S + t) * 256 + gc];
            #pragma unroll
            for (int q = 0; q < 32; q++) acc += pp[q * 128 + tid];
            float v = sigmoidf_(acc);
            if (rank == 0) { float rv = v * h0s[tid]; rh[tid] = rv; st_peer(&rh[tid], peer, rv); }
            else           { us0[tid] = v;            st_peer(&us0[tid], peer, v); }
        }
        cluster_sync_();
        // ---- B: L0 candidate, cols [rank*64, +64), K=128 over rh ----
        mv_t<64, 128, 128>(rh, e0_ck + E * 128 + rank * 64, pp, tid);
        __syncthreads();
        if (tid < 64) {
            int c = rank * 64 + tid;
            float acc = g_ecx[(b * S + t) * H + c];
            #pragma unroll
            for (int q = 0; q < 64; q++) acc += pp[q * 64 + tid];
            float cc = tanhf(acc);
            float u = us0[c];
            float n0 = u * h0s[c] + (1.f - u) * cc;
            n0s[c] = n0; st_peer(&n0s[c], peer, n0);
            cb[c] = n0;  st_peer(&cb[c], peer, n0);
        }
        if (tid < H) cb[H + tid] = h1s[tid];
        cluster_sync_();
        // ---- C: L1 gates over [n0, h1], cols [rank*128, +128), K=256 ----
        mv_t<128, 256, 256>(cb, e1_gk + rank * 128, pp, tid);
        __syncthreads();
        if (tid < 128) {
            int gc = rank * 128 + tid;
            float acc = e1_gb[gc];
            #pragma unroll
            for (int q = 0; q < 32; q++) acc += pp[q * 128 + tid];
            float v = sigmoidf_(acc);
            if (rank == 0) { float rv = v * h1s[tid]; cb[H + tid] = rv; st_peer(&cb[H + tid], peer, rv); }
            else           { us1[tid] = v;            st_peer(&us1[tid], peer, v); }
        }
        cluster_sync_();
        // ---- D: L1 candidate over [n0, r*h1], cols [rank*64, +64), K=256 ----
        mv_t<64, 128, 256>(cb, e1_ck + rank * 64, pp, tid);
        __syncthreads();
        if (tid < 64) {
            int c = rank * 64 + tid;
            float acc = e1_cb[c];
            #pragma unroll
            for (int q = 0; q < 64; q++) acc += pp[q * 64 + tid];
            float cc = tanhf(acc);
            float u = us1[c];
            float n1 = u * h1s[c] + (1.f - u) * cc;
            if (valid) {
                h1s[c] = n1; st_peer(&h1s[c], peer, n1);
                g_mem[(b * S + t) * H + c] = n1;
            } else {
                g_mem[(b * S + t) * H + c] = 0.f;
            }
        }
        if (tid < H && valid) h0s[tid] = n0s[tid];
        cluster_sync_();
    }
    if (rank == 0 && tid < H) {
        g_h0[b * H + tid] = h0s[tid];
        g_h1[b * H + tid] = h1s[tid];
    }
}

// ---------------- keys = memory @ W_mem ----------------
__global__ __launch_bounds__(128) void keys_naive(const float* __restrict__ W_mem) {
    int row = blockIdx.x;
    int j = threadIdx.x;
    float a0 = 0.f, a1 = 0.f, a2 = 0.f, a3 = 0.f;
    #pragma unroll 8
    for (int k = 0; k < H; k += 4) {
        a0 += g_mem[row * H + k]     * W_mem[k * H + j];
        a1 += g_mem[row * H + k + 1] * W_mem[(k + 1) * H + j];
        a2 += g_mem[row * H + k + 2] * W_mem[(k + 2) * H + j];
        a3 += g_mem[row * H + k + 3] * W_mem[(k + 3) * H + j];
    }
    g_keys[row * H + j] = (a0 + a1) + (a2 + a3);
}

// ---------------- fused decoder: 2-CTA cluster per batch element ----------------
__global__ void __cluster_dims__(2, 1, 1) __launch_bounds__(1024, 1) dec_fused(
    const float* __restrict__ d0_gk, const float* __restrict__ d0_ck,
    const float* __restrict__ d1_gk, const float* __restrict__ d1_gb,
    const float* __restrict__ d1_ck, const float* __restrict__ d1_cb,
    const float* __restrict__ W_q, const float* __restrict__ v_att,
    const float* __restrict__ W_attn, const int* __restrict__ x_len)
{
    int b = blockIdx.x >> 1;
    unsigned rank = ctarank_();
    unsigned peer = rank ^ 1u;
    int tid = threadIdx.x;
    int lid = tid & 31;
    int wid = tid >> 5;
    int xlen = x_len[b];

    __shared__ float h0s[H], h1s[H], n0s[H], n1s[H], qs[H], us0[H], us1[H];
    __shared__ float cb[2 * H];
    __shared__ float pp[4096];
    __shared__ float sco[S];

    if (tid < H) {
        float h0 = g_h0[b * H + tid];
        h0s[tid] = h0;
        h1s[tid] = g_h1[b * H + tid];
        cb[tid] = 0.f;           // attn_0 = 0
        cb[H + tid] = h0;        // [attn, h0]
    }
    cluster_sync_();

    for (int t = 0; t < S; t++) {
        // ---- A: L0 gates over [attn, h0], cols [rank*128, +128), K=256 ----
        mv_t<128, 256, 256>(cb, d0_gk + E * 256 + rank * 128, pp, tid);
        __syncthreads();
        if (tid < 128) {
            int gc = rank * 128 + tid;
            float acc = g_dgx[(b * S + t) * 256 + gc];
            #pragma unroll
            for (int q = 0; q < 32; q++) acc += pp[q * 128 + tid];
            float v = sigmoidf_(acc);
            if (rank == 0) { float rv = v * h0s[tid]; cb[H + tid] = rv; st_peer(&cb[H + tid], peer, rv); }
            else           { us0[tid] = v;            st_peer(&us0[tid], peer, v); }
        }
        cluster_sync_();
        // ---- B: L0 candidate over [attn, r*h0], cols [rank*64, +64), K=256 ----
        mv_t<64, 128, 256>(cb, d0_ck + E * 128 + rank * 64, pp, tid);
        __syncthreads();
        if (tid < 64) {
            int c = rank * 64 + tid;
            float acc = g_dcx[(b * S + t) * H + c];
            #pragma unroll
            for (int q = 0; q < 64; q++) acc += pp[q * 64 + tid];
            float cc = tanhf(acc);
            float u = us0[c];
            float n0 = u * h0s[c] + (1.f - u) * cc;
            n0s[c] = n0; st_peer(&n0s[c], peer, n0);
            cb[c] = n0;  st_peer(&cb[c], peer, n0);
        }
        if (tid < H) cb[H + tid] = h1s[tid];
        cluster_sync_();
        // ---- C: L1 gates over [n0, h1], cols [rank*128, +128), K=256 ----
        mv_t<128, 256, 256>(cb, d1_gk + rank * 128, pp, tid);
        __syncthreads();
        if (tid < 128) {
            int gc = rank * 128 + tid;
            float acc = d1_gb[gc];
            #pragma unroll
            for (int q = 0; q < 32; q++) acc += pp[q * 128 + tid];
            float v = sigmoidf_(acc);
            if (rank == 0) { float rv = v * h1s[tid]; cb[H + tid] = rv; st_peer(&cb[H + tid], peer, rv); }
            else           { us1[tid] = v;            st_peer(&us1[tid], peer, v); }
        }
        cluster_sync_();
        // ---- D: L1 candidate over [n0, r*h1], cols [rank*64, +64), K=256 ----
        mv_t<64, 128, 256>(cb, d1_ck + rank * 64, pp, tid);
        __syncthreads();
        if (tid < 64) {
            int c = rank * 64 + tid;
            float acc = d1_cb[c];
            #pragma unroll
            for (int q = 0; q < 64; q++) acc += pp[q * 64 + tid];
            float cc = tanhf(acc);
            float u = us1[c];
            float n1 = u * h1s[c] + (1.f - u) * cc;
            n1s[c] = n1; st_peer(&n1s[c], peer, n1);
        }
        cluster_sync_();
        // ---- Q: query = n1 @ W_q, cols [rank*64, +64), K=128 ----
        mv_t<64, 128, 128>(n1s, W_q + rank * 64, pp, tid);
        __syncthreads();
        if (tid < 64) {
            int c = rank * 64 + tid;
            float acc = 0.f;
            #pragma unroll
            for (int q = 0; q < 64; q++) acc += pp[q * 64 + tid];
            qs[c] = acc; st_peer(&qs[c], peer, acc);
        }
        cluster_sync_();
        // ---- attention scores (computed redundantly in both CTAs) ----
        if (wid < S) {
            int s = wid;
            float acc = 0.f;
            const float* kr = &g_keys[(b * S + s) * H];
            #pragma unroll
            for (int u = 0; u < 4; u++) {
                int uu = lid + u * 32;
                acc += tanhf(kr[uu] + qs[uu]) * v_att[uu];
            }
            #pragma unroll
            for (int off = 16; off > 0; off >>= 1)
                acc += __shfl_xor_sync(0xffffffffu, acc, off);
            if (lid == 0)
                sco[s] = (s >= xlen) ? -3.4028235e38f : acc;
        }
        __syncthreads();
        if (tid == 0) {
            float m = -3.4028235e38f;
            #pragma unroll
            for (int s = 0; s < S; s++) m = fmaxf(m, sco[s]);
            float sum = 0.f;
            #pragma unroll
            for (int s = 0; s < S; s++) { float ev = expf(sco[s] - m); sco[s] = ev; sum += ev; }
            float inv = 1.f / sum;
            #pragma unroll
            for (int s = 0; s < S; s++) sco[s] *= inv;
        }
        __syncthreads();
        // ---- context (redundant in both CTAs) -> cb = [n1, ctx] ----
        if (tid < H) {
            float acc = 0.f;
            #pragma unroll
            for (int s = 0; s < S; s++) acc += sco[s] * g_mem[(b * S + s) * H + tid];
            cb[H + tid] = acc;
            cb[tid] = n1s[tid];
        }
        __syncthreads();
        // ---- NA: na = [n1, ctx] @ W_attn, cols [rank*64, +64), K=256 ----
        mv_t<64, 128, 256>(cb, W_attn + rank * 64, pp, tid);
        __syncthreads();
        if (tid < 64) {
            int c = rank * 64 + tid;
            float acc = 0.f;
            #pragma unroll
            for (int q = 0; q < 64; q++) acc += pp[q * 64 + tid];
            g_na[(b * S + t) * H + c] = acc;
            cb[c] = acc; st_peer(&cb[c], peer, acc);   // next-step attn
        }
        if (tid < H) {
            h0s[tid] = n0s[tid];
            h1s[tid] = n1s[tid];
            cb[H + tid] = n0s[tid];                    // next-step h0
        }
        cluster_sync_();
    }
}

// ---------------- projection GEMM: f32x2 packed FFMA (2x fp32 MAC rate) ----------------
__device__ __forceinline__ void ffma2(unsigned long long& d, unsigned long long a, unsigned long long b) {
    asm("fma.rn.f32x2 %0, %1, %2, %0;" : "+l"(d) : "l"(a), "l"(b));
}
__device__ __forceinline__ unsigned long long dup2(float x) {
    unsigned long long r;
    asm("mov.b64 %0, {%1, %1};" : "=l"(r) : "r"(__float_as_uint(x)));
    return r;
}

#define PROJ_SMEM ((128 * 129 + 128 * 128) * 4)

__global__ __launch_bounds__(256, 1) void proj_kernel(
    const float* __restrict__ bias, const int* __restrict__ y_len,
    float* __restrict__ out)
{
    extern __shared__ float sm[];
    float* As = sm;                                                   // [128][129]
    unsigned long long* As2 = (unsigned long long*)(sm + 128 * 129);  // [k][64] row-pairs

    int bm0 = blockIdx.y * 128;
    int bn0 = blockIdx.x * 128;
    int tid = threadIdx.x;

    for (int e = tid; e < 128 * 128; e += 256) {
        int r = e >> 7, k = e & 127;
        As[r * 129 + k] = g_na[(bm0 + r) * H + k];
    }
    __syncthreads();
    for (int e = tid; e < 128 * 64; e += 256) {
        int p = e & 63, k = e >> 6;
        float2 v = make_float2(As[(2 * p) * 129 + k], As[(2 * p + 1) * 129 + k]);
        As2[k * 64 + p] = *reinterpret_cast<unsigned long long*>(&v);
    }
    __syncthreads();

    int tx = tid & 31, wid = tid >> 5;
    int p0 = wid * 8;
    int c0 = bn0 + tx * 4;

    unsigned long long acc[8][4];
    #pragma unroll
    for (int p = 0; p < 8; p++)
        #pragma unroll
        for (int c = 0; c < 4; c++) acc[p][c] = 0ull;

    const float4* W4 = reinterpret_cast<const float4*>(g_Wpad);
    int wbase = (c0 >> 2);

    #pragma unroll 4
    for (int k = 0; k < 128; k++) {
        float4 w = W4[k * (VP / 4) + wbase];
        unsigned long long wd0 = dup2(w.x), wd1 = dup2(w.y), wd2 = dup2(w.z), wd3 = dup2(w.w);
        const unsigned long long* a2 = &As2[k * 64 + p0];
        #pragma unroll
        for (int p = 0; p < 8; p++) {
            unsigned long long av = a2[p];
            ffma2(acc[p][0], av, wd0);
            ffma2(acc[p][1], av, wd1);
            ffma2(acc[p][2], av, wd2);
            ffma2(acc[p][3], av, wd3);
        }
    }

    #pragma unroll
    for (int p = 0; p < 8; p++) {
        int r0 = wid * 16 + 2 * p;
        #pragma unroll
        for (int half = 0; half < 2; half++) {
            int rr = r0 + half;
            int row = bm0 + rr;
            int b = row / S, t = row - b * S;
            bool valid = (t < y_len[b]);
            float* o = out + (long)row * V;
            #pragma unroll
            for (int c = 0; c < 4; c++) {
                int cc = c0 + c;
                if (cc < V) {
                    unsigned long long a = acc[p][c];
                    unsigned int bits = half ? (unsigned int)(a >> 32) : (unsigned int)(a & 0xffffffffull);
                    o[cc] = valid ? (__uint_as_float(bits) + bias[cc]) : 0.f;
                }
            }
        }
    }
}

// ---------------- host launch ----------------
extern "C" void kernel_launch(void* const* d_in, const int* in_sizes, int n_in,
                              void* d_out, int out_size) {
    const int*   x      = (const int*)d_in[0];
    const int*   x_len  = (const int*)d_in[1];
    const int*   y      = (const int*)d_in[2];
    const int*   y_len  = (const int*)d_in[3];
    const float* emb    = (const float*)d_in[4];
    const float* e0_gk  = (const float*)d_in[5];
    const float* e0_gb  = (const float*)d_in[6];
    const float* e0_ck  = (const float*)d_in[7];
    const float* e0_cb  = (const float*)d_in[8];
    const float* e1_gk  = (const float*)d_in[9];
    const float* e1_gb  = (const float*)d_in[10];
    const float* e1_ck  = (const float*)d_in[11];
    const float* e1_cb  = (const float*)d_in[12];
    const float* d0_gk  = (const float*)d_in[13];
    const float* d0_gb  = (const float*)d_in[14];
    const float* d0_ck  = (const float*)d_in[15];
    const float* d0_cb  = (const float*)d_in[16];
    const float* d1_gk  = (const float*)d_in[17];
    const float* d1_gb  = (const float*)d_in[18];
    const float* d1_ck  = (const float*)d_in[19];
    const float* d1_cb  = (const float*)d_in[20];
    const float* W_mem  = (const float*)d_in[21];
    const float* W_q    = (const float*)d_in[22];
    const float* v_att  = (const float*)d_in[23];
    const float* W_attn = (const float*)d_in[24];
    const float* W_proj = (const float*)d_in[25];
    const float* b_proj = (const float*)d_in[26];
    float* out = (float*)d_out;

    cudaFuncSetAttribute(proj_kernel, cudaFuncAttributeMaxDynamicSharedMemorySize, PROJ_SMEM);

    padW_kernel<<<dim3((VP + 255) / 256, 128), 256>>>(W_proj);

    xpart_all_kernel<<<dim3((B * S) / 8, 4), 256>>>(
        x, y, emb, e0_gk, e0_gb, e0_ck, e0_cb, d0_gk, d0_gb, d0_ck, d0_cb);

    enc_fused<<<2 * B, 1024>>>(e0_gk, e0_ck, e1_gk, e1_gb, e1_ck, e1_cb, x_len);

    keys_naive<<<B * S, 128>>>(W_mem);

    dec_fused<<<2 * B, 1024>>>(d0_gk, d0_ck, d1_gk, d1_gb, d1_ck, d1_cb,
                               W_q, v_att, W_attn, x_len);

    proj_kernel<<<dim3(VP / 128, (B * S) / 128), 256, PROJ_SMEM>>>(b_proj, y_len, out);
}

// round 12
// speedup vs baseline: 2.7413x; 1.2384x over previous
#include <cuda_runtime.h>
#include <cuda_bf16.h>
#include <math.h>

#define B 64
#define S 20
#define H 128
#define E 300
#define V 50257
#define VP 50304   // V padded to multiple of 128

// ---------------- device scratch (static, no runtime alloc) ----------------
__device__ float g_h0[B * H];
__device__ float g_h1[B * H];
__device__ float g_mem[B * S * H];
__device__ float g_keys[B * S * H];
__device__ float g_egx[B * S * 2 * H];
__device__ float g_ecx[B * S * H];
__device__ float g_dgx[B * S * 2 * H];
__device__ float g_dcx[B * S * H];
__device__ float g_na[B * S * H];
__device__ float g_Wpad[128 * VP];

// ---------------- fast activations (HW tanh, ~1e-5 rel err, damped by gates) ----------------
__device__ __forceinline__ float tanh_fast(float x) {
    float y; asm("tanh.approx.f32 %0, %1;" : "=f"(y) : "f"(x)); return y;
}
__device__ __forceinline__ float sigmoid_fast(float x) {
    return fmaf(0.5f, tanh_fast(0.5f * x), 0.5f);
}

// ---------------- cluster helpers ----------------
__device__ __forceinline__ unsigned ctarank_() {
    unsigned r; asm("mov.u32 %0, %%cluster_ctarank;" : "=r"(r)); return r;
}
__device__ __forceinline__ void cluster_sync_() {
    asm volatile("barrier.cluster.arrive.aligned;" ::: "memory");
    asm volatile("barrier.cluster.wait.aligned;" ::: "memory");
}
__device__ __forceinline__ void st_peer(float* p, unsigned peer, float v) {
    unsigned la = (unsigned)__cvta_generic_to_shared(p);
    unsigned ra;
    asm("mapa.shared::cluster.u32 %0, %1, %2;" : "=r"(ra) : "r"(la), "r"(peer));
    asm volatile("st.shared::cluster.f32 [%0], %1;" :: "r"(ra), "f"(v));
}

// ---------------- matvec partials, fixed 16 k-chunks (reduction depth 16) ----------------
// NCT columns starting at W (caller pre-offsets); LDW row stride; K depth.
// Active threads = (NCT/4) * 16; each does CH = K/16 independent LDG.128.
template<int NCT, int LDW, int K>
__device__ __forceinline__ void mv16(
    const float* __restrict__ src, const float* __restrict__ W,
    float* __restrict__ pp, int tid)
{
    constexpr int NCG = NCT / 4;
    constexpr int CH  = K / 16;
    if (tid < NCG * 16) {
        int cg = tid & (NCG - 1);
        int kq = tid / NCG;
        const float4* Wb = reinterpret_cast<const float4*>(W + (kq * CH) * LDW) + cg;
        const float* s = src + kq * CH;
        float4 a = make_float4(0.f, 0.f, 0.f, 0.f);
        #pragma unroll
        for (int k = 0; k < CH; k++) {
            float sv = s[k];
            float4 w = Wb[k * (LDW / 4)];
            a.x += sv * w.x; a.y += sv * w.y; a.z += sv * w.z; a.w += sv * w.w;
        }
        reinterpret_cast<float4*>(pp)[kq * NCG + cg] = a;
    }
}

// ---------------- pad W_proj ----------------
__global__ void padW_kernel(const float* __restrict__ Wp) {
    int c = blockIdx.x * blockDim.x + threadIdx.x;
    int k = blockIdx.y;
    if (c >= VP) return;
    g_Wpad[k * VP + c] = (c < V) ? Wp[(long)k * V + c] : 0.f;
}

// ---------------- x-part precompute (device-side symbol resolution!) ----------------
__global__ void xpart_all_kernel(
    const int* __restrict__ x, const int* __restrict__ y,
    const float* __restrict__ emb,
    const float* __restrict__ e0_gk, const float* __restrict__ e0_gb,
    const float* __restrict__ e0_ck, const float* __restrict__ e0_cb,
    const float* __restrict__ d0_gk, const float* __restrict__ d0_gb,
    const float* __restrict__ d0_ck, const float* __restrict__ d0_cb)
{
    int which = blockIdx.y;
    float* out;
    const float* W; const float* bias; const int* ids; int ncols;
    switch (which) {
        case 0:  out = g_egx; W = e0_gk; bias = e0_gb; ids = x; ncols = 256; break;
        case 1:  out = g_ecx; W = e0_ck; bias = e0_cb; ids = x; ncols = 128; break;
        case 2:  out = g_dgx; W = d0_gk; bias = d0_gb; ids = y; ncols = 256; break;
        default: out = g_dcx; W = d0_ck; bias = d0_cb; ids = y; ncols = 128; break;
    }
    __shared__ float xs[8][E];
    int row0 = blockIdx.x * 8;
    int tid = threadIdx.x;
    for (int e = tid; e < 8 * E; e += 256) {
        int r = e / E, k = e - r * E;
        xs[r][k] = emb[(long)ids[row0 + r] * E + k];
    }
    __syncthreads();
    if (tid < ncols) {
        int j = tid;
        float acc[8];
        #pragma unroll
        for (int r = 0; r < 8; r++) acc[r] = 0.f;
        #pragma unroll 10
        for (int k = 0; k < E; k++) {
            float w = W[k * ncols + j];
            #pragma unroll
            for (int r = 0; r < 8; r++) acc[r] += xs[r][k] * w;
        }
        float bv = bias[j];
        #pragma unroll
        for (int r = 0; r < 8; r++) out[(row0 + r) * ncols + j] = acc[r] + bv;
    }
}

// ---------------- fused encoder + keys: 2-CTA cluster per batch element ----------------
__global__ void __cluster_dims__(2, 1, 1) __launch_bounds__(1024, 1) enc_fused(
    const float* __restrict__ e0_gk, const float* __restrict__ e0_ck,
    const float* __restrict__ e1_gk, const float* __restrict__ e1_gb,
    const float* __restrict__ e1_ck, const float* __restrict__ e1_cb,
    const float* __restrict__ W_mem, const int* __restrict__ x_len)
{
    int b = blockIdx.x >> 1;
    unsigned rank = ctarank_();
    unsigned peer = rank ^ 1u;
    int tid = threadIdx.x;
    int xlen = x_len[b];

    __shared__ float h0s[H], h1s[H], n0s[H], us0[H], us1[H], rh[H];
    __shared__ float cb[2 * H];
    __shared__ float pp[2048];
    __shared__ float mems[S][H];

    if (tid < H) { h0s[tid] = 0.f; h1s[tid] = 0.f; }
    cluster_sync_();

    for (int t = 0; t < S; t++) {
        bool valid = (t < xlen);
        // A: L0 gates (h0-part), 128 cols/rank, K=128
        mv16<128, 256, 128>(h0s, e0_gk + E * 256 + rank * 128, pp, tid);
        __syncthreads();
        if (tid < 128) {
            int gc = rank * 128 + tid;
            float acc = g_egx[(b * S + t) * 256 + gc];
            #pragma unroll
            for (int q = 0; q < 16; q++) acc += pp[q * 128 + tid];
            float v = sigmoid_fast(acc);
            if (rank == 0) { float rv = v * h0s[tid]; rh[tid] = rv; st_peer(&rh[tid], peer, rv); }
            else           { us0[tid] = v;            st_peer(&us0[tid], peer, v); }
        }
        cluster_sync_();
        // B: L0 candidate, 64 cols/rank, K=128 over rh
        mv16<64, 128, 128>(rh, e0_ck + E * 128 + rank * 64, pp, tid);
        __syncthreads();
        if (tid < 64) {
            int c = rank * 64 + tid;
            float acc = g_ecx[(b * S + t) * H + c];
            #pragma unroll
            for (int q = 0; q < 16; q++) acc += pp[q * 64 + tid];
            float cc = tanh_fast(acc);
            float u = us0[c];
            float n0 = u * h0s[c] + (1.f - u) * cc;
            n0s[c] = n0; st_peer(&n0s[c], peer, n0);
            cb[c] = n0;  st_peer(&cb[c], peer, n0);
        }
        if (tid < H) cb[H + tid] = h1s[tid];
        cluster_sync_();
        // C: L1 gates over [n0, h1], 128 cols/rank, K=256
        mv16<128, 256, 256>(cb, e1_gk + rank * 128, pp, tid);
        __syncthreads();
        if (tid < 128) {
            int gc = rank * 128 + tid;
            float acc = e1_gb[gc];
            #pragma unroll
            for (int q = 0; q < 16; q++) acc += pp[q * 128 + tid];
            float v = sigmoid_fast(acc);
            if (rank == 0) { float rv = v * h1s[tid]; cb[H + tid] = rv; st_peer(&cb[H + tid], peer, rv); }
            else           { us1[tid] = v;            st_peer(&us1[tid], peer, v); }
        }
        cluster_sync_();
        // D: L1 candidate over [n0, r*h1], 64 cols/rank, K=256
        mv16<64, 128, 256>(cb, e1_ck + rank * 64, pp, tid);
        __syncthreads();
        if (tid < 64) {
            int c = rank * 64 + tid;
            float acc = e1_cb[c];
            #pragma unroll
            for (int q = 0; q < 16; q++) acc += pp[q * 64 + tid];
            float cc = tanh_fast(acc);
            float u = us1[c];
            float n1 = u * h1s[c] + (1.f - u) * cc;
            float mv;
            if (valid) {
                h1s[c] = n1; st_peer(&h1s[c], peer, n1);
                mv = n1;
            } else {
                mv = 0.f;
            }
            mems[t][c] = mv; st_peer(&mems[t][c], peer, mv);
            g_mem[(b * S + t) * H + c] = mv;
        }
        if (tid < H && valid) h0s[tid] = n0s[tid];
        cluster_sync_();
    }
    if (rank == 0 && tid < H) {
        g_h0[b * H + tid] = h0s[tid];
        g_h1[b * H + tid] = h1s[tid];
    }
    // keys = mems @ W_mem, 64 cols per rank, from smem-resident mems
    for (int idx = tid; idx < S * 64; idx += 1024) {
        int t = idx >> 6, c = idx & 63;
        int gc = (int)rank * 64 + c;
        float a0 = 0.f, a1 = 0.f, a2 = 0.f, a3 = 0.f;
        #pragma unroll 8
        for (int k = 0; k < H; k += 4) {
            a0 += mems[t][k]     * W_mem[k * H + gc];
            a1 += mems[t][k + 1] * W_mem[(k + 1) * H + gc];
            a2 += mems[t][k + 2] * W_mem[(k + 2) * H + gc];
            a3 += mems[t][k + 3] * W_mem[(k + 3) * H + gc];
        }
        g_keys[(b * S + t) * H + gc] = (a0 + a1) + (a2 + a3);
    }
}

// ---------------- fused decoder: 2-CTA cluster per batch element ----------------
__global__ void __cluster_dims__(2, 1, 1) __launch_bounds__(1024, 1) dec_fused(
    const float* __restrict__ d0_gk, const float* __restrict__ d0_ck,
    const float* __restrict__ d1_gk, const float* __restrict__ d1_gb,
    const float* __restrict__ d1_ck, const float* __restrict__ d1_cb,
    const float* __restrict__ W_q, const float* __restrict__ v_att,
    const float* __restrict__ W_attn, const int* __restrict__ x_len)
{
    int b = blockIdx.x >> 1;
    unsigned rank = ctarank_();
    unsigned peer = rank ^ 1u;
    int tid = threadIdx.x;
    int lid = tid & 31;
    int wid = tid >> 5;
    int xlen = x_len[b];

    __shared__ float h0s[H], h1s[H], n0s[H], n1s[H], qs[H], us0[H], us1[H];
    __shared__ float cb[2 * H];
    __shared__ float pp[2048];
    __shared__ float sco[S];

    if (tid < H) {
        float h0 = g_h0[b * H + tid];
        h0s[tid] = h0;
        h1s[tid] = g_h1[b * H + tid];
        cb[tid] = 0.f;
        cb[H + tid] = h0;
    }
    cluster_sync_();

    for (int t = 0; t < S; t++) {
        // A: L0 gates over [attn, h0], 128 cols/rank, K=256
        mv16<128, 256, 256>(cb, d0_gk + E * 256 + rank * 128, pp, tid);
        __syncthreads();
        if (tid < 128) {
            int gc = rank * 128 + tid;
            float acc = g_dgx[(b * S + t) * 256 + gc];
            #pragma unroll
            for (int q = 0; q < 16; q++) acc += pp[q * 128 + tid];
            float v = sigmoid_fast(acc);
            if (rank == 0) { float rv = v * h0s[tid]; cb[H + tid] = rv; st_peer(&cb[H + tid], peer, rv); }
            else           { us0[tid] = v;            st_peer(&us0[tid], peer, v); }
        }
        cluster_sync_();
        // B: L0 candidate over [attn, r*h0], 64 cols/rank, K=256
        mv16<64, 128, 256>(cb, d0_ck + E * 128 + rank * 64, pp, tid);
        __syncthreads();
        if (tid < 64) {
            int c = rank * 64 + tid;
            float acc = g_dcx[(b * S + t) * H + c];
            #pragma unroll
            for (int q = 0; q < 16; q++) acc += pp[q * 64 + tid];
            float cc = tanh_fast(acc);
            float u = us0[c];
            float n0 = u * h0s[c] + (1.f - u) * cc;
            n0s[c] = n0; st_peer(&n0s[c], peer, n0);
            cb[c] = n0;  st_peer(&cb[c], peer, n0);
        }
        if (tid < H) cb[H + tid] = h1s[tid];
        cluster_sync_();
        // C: L1 gates over [n0, h1], 128 cols/rank, K=256
        mv16<128, 256, 256>(cb, d1_gk + rank * 128, pp, tid);
        __syncthreads();
        if (tid < 128) {
            int gc = rank * 128 + tid;
            float acc = d1_gb[gc];
            #pragma unroll
            for (int q = 0; q < 16; q++) acc += pp[q * 128 + tid];
            float v = sigmoid_fast(acc);
            if (rank == 0) { float rv = v * h1s[tid]; cb[H + tid] = rv; st_peer(&cb[H + tid], peer, rv); }
            else           { us1[tid] = v;            st_peer(&us1[tid], peer, v); }
        }
        cluster_sync_();
        // D: L1 candidate over [n0, r*h1], 64 cols/rank, K=256
        mv16<64, 128, 256>(cb, d1_ck + rank * 64, pp, tid);
        __syncthreads();
        if (tid < 64) {
            int c = rank * 64 + tid;
            float acc = d1_cb[c];
            #pragma unroll
            for (int q = 0; q < 16; q++) acc += pp[q * 64 + tid];
            float cc = tanh_fast(acc);
            float u = us1[c];
            float n1 = u * h1s[c] + (1.f - u) * cc;
            n1s[c] = n1; st_peer(&n1s[c], peer, n1);
        }
        cluster_sync_();
        // Q: query = n1 @ W_q, 64 cols/rank, K=128
        mv16<64, 128, 128>(n1s, W_q + rank * 64, pp, tid);
        __syncthreads();
        if (tid < 64) {
            int c = rank * 64 + tid;
            float acc = 0.f;
            #pragma unroll
            for (int q = 0; q < 16; q++) acc += pp[q * 64 + tid];
            qs[c] = acc; st_peer(&qs[c], peer, acc);
        }
        cluster_sync_();
        // attention scores (redundant both CTAs)
        if (wid < S) {
            int s = wid;
            float acc = 0.f;
            const float* kr = &g_keys[(b * S + s) * H];
            #pragma unroll
            for (int u = 0; u < 4; u++) {
                int uu = lid + u * 32;
                acc += tanh_fast(kr[uu] + qs[uu]) * v_att[uu];
            }
            #pragma unroll
            for (int off = 16; off > 0; off >>= 1)
                acc += __shfl_xor_sync(0xffffffffu, acc, off);
            if (lid == 0)
                sco[s] = (s >= xlen) ? -3.4028235e38f : acc;
        }
        __syncthreads();
        if (tid == 0) {
            float m = -3.4028235e38f;
            #pragma unroll
            for (int s = 0; s < S; s++) m = fmaxf(m, sco[s]);
            float sum = 0.f;
            #pragma unroll
            for (int s = 0; s < S; s++) { float ev = __expf(sco[s] - m); sco[s] = ev; sum += ev; }
            float inv = __fdividef(1.f, sum);
            #pragma unroll
            for (int s = 0; s < S; s++) sco[s] *= inv;
        }
        __syncthreads();
        // context -> cb = [n1, ctx]
        if (tid < H) {
            float acc = 0.f;
            #pragma unroll
            for (int s = 0; s < S; s++) acc += sco[s] * g_mem[(b * S + s) * H + tid];
            cb[H + tid] = acc;
            cb[tid] = n1s[tid];
        }
        __syncthreads();
        // NA: na = [n1, ctx] @ W_attn, 64 cols/rank, K=256
        mv16<64, 128, 256>(cb, W_attn + rank * 64, pp, tid);
        __syncthreads();
        if (tid < 64) {
            int c = rank * 64 + tid;
            float acc = 0.f;
            #pragma unroll
            for (int q = 0; q < 16; q++) acc += pp[q * 64 + tid];
            g_na[(b * S + t) * H + c] = acc;
            cb[c] = acc; st_peer(&cb[c], peer, acc);
        }
        if (tid < H) {
            h0s[tid] = n0s[tid];
            h1s[tid] = n1s[tid];
            cb[H + tid] = n0s[tid];
        }
        cluster_sync_();
    }
}

// ---------------- projection GEMM: f32x2 packed FFMA, 2 CTAs/SM ----------------
__device__ __forceinline__ void ffma2(unsigned long long& d, unsigned long long a, unsigned long long b) {
    asm("fma.rn.f32x2 %0, %1, %2, %0;" : "+l"(d) : "l"(a), "l"(b));
}
__device__ __forceinline__ unsigned long long dup2(float x) {
    unsigned long long r;
    asm("mov.b64 %0, {%1, %1};" : "=l"(r) : "r"(__float_as_uint(x)));
    return r;
}

// smem: As2 (128 k x 64 row-pairs, ull) = 64 KB + slab 128 x 33 floats = 16.9 KB
#define PROJ_SMEM (128 * 64 * 8 + 128 * 33 * 4)

__global__ __launch_bounds__(256, 2) void proj_kernel(
    const float* __restrict__ bias, const int* __restrict__ y_len,
    float* __restrict__ out)
{
    extern __shared__ float sm[];
    unsigned long long* As2 = (unsigned long long*)sm;       // [k][64] row-pairs
    float* As_s = sm + 128 * 64 * 2;                          // [128][33] slab

    int bm0 = blockIdx.y * 128;
    int bn0 = blockIdx.x * 128;
    int tid = threadIdx.x;

    // slab-wise load + repack (4 slabs of 32 k's) — peak smem 82 KB -> 2 CTAs/SM
    #pragma unroll
    for (int ks = 0; ks < 128; ks += 32) {
        for (int e = tid; e < 128 * 32; e += 256) {
            int r = e >> 5, k0 = e & 31;
            As_s[r * 33 + k0] = g_na[(bm0 + r) * H + ks + k0];
        }
        __syncthreads();
        for (int e = tid; e < 32 * 64; e += 256) {
            int p = e & 63, k0 = e >> 6;
            float2 v = make_float2(As_s[(2 * p) * 33 + k0], As_s[(2 * p + 1) * 33 + k0]);
            As2[(ks + k0) * 64 + p] = *reinterpret_cast<unsigned long long*>(&v);
        }
        __syncthreads();
    }

    int tx = tid & 31, wid = tid >> 5;
    int p0 = wid * 8;
    int c0 = bn0 + tx * 4;

    unsigned long long acc[8][4];
    #pragma unroll
    for (int p = 0; p < 8; p++)
        #pragma unroll
        for (int c = 0; c < 4; c++) acc[p][c] = 0ull;

    const float4* W4 = reinterpret_cast<const float4*>(g_Wpad);
    int wbase = (c0 >> 2);

    #pragma unroll 4
    for (int k = 0; k < 128; k++) {
        float4 w = W4[k * (VP / 4) + wbase];
        unsigned long long wd0 = dup2(w.x), wd1 = dup2(w.y), wd2 = dup2(w.z), wd3 = dup2(w.w);
        const unsigned long long* a2 = &As2[k * 64 + p0];
        #pragma unroll
        for (int p = 0; p < 8; p++) {
            unsigned long long av = a2[p];
            ffma2(acc[p][0], av, wd0);
            ffma2(acc[p][1], av, wd1);
            ffma2(acc[p][2], av, wd2);
            ffma2(acc[p][3], av, wd3);
        }
    }

    #pragma unroll
    for (int p = 0; p < 8; p++) {
        int r0 = wid * 16 + 2 * p;
        #pragma unroll
        for (int half = 0; half < 2; half++) {
            int rr = r0 + half;
            int row = bm0 + rr;
            int bb = row / S, t = row - bb * S;
            bool valid = (t < y_len[bb]);
            float* o = out + (long)row * V;
            #pragma unroll
            for (int c = 0; c < 4; c++) {
                int cc = c0 + c;
                if (cc < V) {
                    unsigned long long a = acc[p][c];
                    unsigned int bits = half ? (unsigned int)(a >> 32) : (unsigned int)(a & 0xffffffffull);
                    o[cc] = valid ? (__uint_as_float(bits) + bias[cc]) : 0.f;
                }
            }
        }
    }
}

// ---------------- host launch ----------------
extern "C" void kernel_launch(void* const* d_in, const int* in_sizes, int n_in,
                              void* d_out, int out_size) {
    const int*   x      = (const int*)d_in[0];
    const int*   x_len  = (const int*)d_in[1];
    const int*   y      = (const int*)d_in[2];
    const int*   y_len  = (const int*)d_in[3];
    const float* emb    = (const float*)d_in[4];
    const float* e0_gk  = (const float*)d_in[5];
    const float* e0_gb  = (const float*)d_in[6];
    const float* e0_ck  = (const float*)d_in[7];
    const float* e0_cb  = (const float*)d_in[8];
    const float* e1_gk  = (const float*)d_in[9];
    const float* e1_gb  = (const float*)d_in[10];
    const float* e1_ck  = (const float*)d_in[11];
    const float* e1_cb  = (const float*)d_in[12];
    const float* d0_gk  = (const float*)d_in[13];
    const float* d0_gb  = (const float*)d_in[14];
    const float* d0_ck  = (const float*)d_in[15];
    const float* d0_cb  = (const float*)d_in[16];
    const float* d1_gk  = (const float*)d_in[17];
    const float* d1_gb  = (const float*)d_in[18];
    const float* d1_ck  = (const float*)d_in[19];
    const float* d1_cb  = (const float*)d_in[20];
    const float* W_mem  = (const float*)d_in[21];
    const float* W_q    = (const float*)d_in[22];
    const float* v_att  = (const float*)d_in[23];
    const float* W_attn = (const float*)d_in[24];
    const float* W_proj = (const float*)d_in[25];
    const float* b_proj = (const float*)d_in[26];
    float* out = (float*)d_out;

    cudaFuncSetAttribute(proj_kernel, cudaFuncAttributeMaxDynamicSharedMemorySize, PROJ_SMEM);

    // launch order chosen so launch #4 (= ncu capture target) is dec_fused
    padW_kernel<<<dim3((VP + 255) / 256, 128), 256>>>(W_proj);                       // 1
    xpart_all_kernel<<<dim3((B * S) / 8, 4), 256>>>(
        x, y, emb, e0_gk, e0_gb, e0_ck, e0_cb, d0_gk, d0_gb, d0_ck, d0_cb);          // 2
    enc_fused<<<2 * B, 1024>>>(e0_gk, e0_ck, e1_gk, e1_gb, e1_ck, e1_cb,
                               W_mem, x_len);                                        // 3 (incl. keys)
    dec_fused<<<2 * B, 1024>>>(d0_gk, d0_ck, d1_gk, d1_gb, d1_ck, d1_cb,
                               W_q, v_att, W_attn, x_len);                           // 4 <- profiled
    proj_kernel<<<dim3(VP / 128, (B * S) / 128), 256, PROJ_SMEM>>>(b_proj, y_len, out); // 5
}

// round 14
// speedup vs baseline: 3.0754x; 1.1219x over previous
#include <cuda_runtime.h>
#include <cuda_bf16.h>
#include <math.h>
#include <stdint.h>

#define B 64
#define S 20
#define H 128
#define E 300
#define V 50257
#define VP 50304   // V padded to multiple of 128
#define NTILES (VP / 128)   // 393

// ---------------- device scratch (static, no runtime alloc) ----------------
__device__ float g_h0[B * H];
__device__ float g_h1[B * H];
__device__ float g_mem[B * S * H];
__device__ float g_keys[B * S * H];
__device__ float g_egx[B * S * 2 * H];
__device__ float g_ecx[B * S * H];
__device__ float g_dgx[B * S * 2 * H];
__device__ float g_dcx[B * S * H];
__device__ float g_na[B * S * H];
// plain [n][k] bf16 hi/lo W_proj tiles (32KB per tile each)
__device__ unsigned short g_Bhi[NTILES * 16384];
__device__ unsigned short g_Blo[NTILES * 16384];

// ---------------- fast activations ----------------
__device__ __forceinline__ float tanh_fast(float x) {
    float y; asm("tanh.approx.f32 %0, %1;" : "=f"(y) : "f"(x)); return y;
}
__device__ __forceinline__ float sigmoid_fast(float x) {
    return fmaf(0.5f, tanh_fast(0.5f * x), 0.5f);
}

// ---------------- cluster helpers ----------------
__device__ __forceinline__ unsigned ctarank_() {
    unsigned r; asm("mov.u32 %0, %%cluster_ctarank;" : "=r"(r)); return r;
}
__device__ __forceinline__ void cluster_sync_() {
    asm volatile("barrier.cluster.arrive.aligned;" ::: "memory");
    asm volatile("barrier.cluster.wait.aligned;" ::: "memory");
}
__device__ __forceinline__ void st_peer(float* p, unsigned peer, float v) {
    unsigned la = (unsigned)__cvta_generic_to_shared(p);
    unsigned ra;
    asm("mapa.shared::cluster.u32 %0, %1, %2;" : "=r"(ra) : "r"(la), "r"(peer));
    asm volatile("st.shared::cluster.f32 [%0], %1;" :: "r"(ra), "f"(v));
}

// ---------------- warp-level bf16 MMA (sm_80+ HMMA; works on plain sm_103) ----------------
__device__ __forceinline__ void mma16816(float* c, const uint32_t* a, const uint32_t* b) {
    asm volatile(
        "mma.sync.aligned.m16n8k16.row.col.f32.bf16.bf16.f32 "
        "{%0,%1,%2,%3}, {%4,%5,%6,%7}, {%8,%9}, {%0,%1,%2,%3};"
        : "+f"(c[0]), "+f"(c[1]), "+f"(c[2]), "+f"(c[3])
        : "r"(a[0]), "r"(a[1]), "r"(a[2]), "r"(a[3]), "r"(b[0]), "r"(b[1]));
}

// ---------------- matvec partials, fixed 16 k-chunks ----------------
template<int NCT, int LDW, int K>
__device__ __forceinline__ void mv16(
    const float* __restrict__ src, const float* __restrict__ W,
    float* __restrict__ pp, int tid)
{
    constexpr int NCG = NCT / 4;
    constexpr int CH  = K / 16;
    if (tid < NCG * 16) {
        int cg = tid & (NCG - 1);
        int kq = tid / NCG;
        const float4* Wb = reinterpret_cast<const float4*>(W + (kq * CH) * LDW) + cg;
        const float* s = src + kq * CH;
        float4 a = make_float4(0.f, 0.f, 0.f, 0.f);
        #pragma unroll
        for (int k = 0; k < CH; k++) {
            float sv = s[k];
            float4 w = Wb[k * (LDW / 4)];
            a.x += sv * w.x; a.y += sv * w.y; a.z += sv * w.z; a.w += sv * w.w;
        }
        reinterpret_cast<float4*>(pp)[kq * NCG + cg] = a;
    }
}

// ---------------- prepB: W_proj -> plain [n][k] bf16 hi/lo tiles ----------------
// Tile nt covers cols [nt*128, +128). B[n][k] = bf16(W[k][c0+n]); lo = residual.
__global__ void prepB_kernel(const float* __restrict__ Wp) {
    extern __shared__ unsigned short sh[];
    unsigned short* s_hi = sh;                 // [128 n][stride 136]
    unsigned short* s_lo = sh + 128 * 136;
    int nt = blockIdx.x;
    int c0 = nt * 128;
    int tid = threadIdx.x;

    for (int idx = tid; idx < 128 * 128; idx += 256) {
        int k = idx >> 7, cc = idx & 127;
        int c = c0 + cc;
        float v = (c < V) ? Wp[(long)k * V + c] : 0.f;
        __nv_bfloat16 h = __float2bfloat16(v);
        float lf = v - __bfloat162float(h);
        __nv_bfloat16 l = __float2bfloat16(lf);
        s_hi[cc * 136 + k] = *reinterpret_cast<unsigned short*>(&h);
        s_lo[cc * 136 + k] = *reinterpret_cast<unsigned short*>(&l);
    }
    __syncthreads();

    unsigned short* dh = g_Bhi + (long)nt * 16384;
    unsigned short* dl = g_Blo + (long)nt * 16384;
    for (int idx = tid; idx < 128 * 16; idx += 256) {
        int n = idx >> 4, ch = idx & 15;   // ch = 8 bf16 k's (16B)
        *reinterpret_cast<uint4*>(dh + n * 128 + ch * 8) =
            *reinterpret_cast<const uint4*>(s_hi + n * 136 + ch * 8);
        *reinterpret_cast<uint4*>(dl + n * 128 + ch * 8) =
            *reinterpret_cast<const uint4*>(s_lo + n * 136 + ch * 8);
    }
}

// ---------------- x-part precompute (device-side symbol resolution!) ----------------
__global__ void xpart_all_kernel(
    const int* __restrict__ x, const int* __restrict__ y,
    const float* __restrict__ emb,
    const float* __restrict__ e0_gk, const float* __restrict__ e0_gb,
    const float* __restrict__ e0_ck, const float* __restrict__ e0_cb,
    const float* __restrict__ d0_gk, const float* __restrict__ d0_gb,
    const float* __restrict__ d0_ck, const float* __restrict__ d0_cb)
{
    int which = blockIdx.y;
    float* out;
    const float* W; const float* bias; const int* ids; int ncols;
    switch (which) {
        case 0:  out = g_egx; W = e0_gk; bias = e0_gb; ids = x; ncols = 256; break;
        case 1:  out = g_ecx; W = e0_ck; bias = e0_cb; ids = x; ncols = 128; break;
        case 2:  out = g_dgx; W = d0_gk; bias = d0_gb; ids = y; ncols = 256; break;
        default: out = g_dcx; W = d0_ck; bias = d0_cb; ids = y; ncols = 128; break;
    }
    __shared__ float xs[8][E];
    int row0 = blockIdx.x * 8;
    int tid = threadIdx.x;
    for (int e = tid; e < 8 * E; e += 256) {
        int r = e / E, k = e - r * E;
        xs[r][k] = emb[(long)ids[row0 + r] * E + k];
    }
    __syncthreads();
    if (tid < ncols) {
        int j = tid;
        float acc[8];
        #pragma unroll
        for (int r = 0; r < 8; r++) acc[r] = 0.f;
        #pragma unroll 10
        for (int k = 0; k < E; k++) {
            float w = W[k * ncols + j];
            #pragma unroll
            for (int r = 0; r < 8; r++) acc[r] += xs[r][k] * w;
        }
        float bv = bias[j];
        #pragma unroll
        for (int r = 0; r < 8; r++) out[(row0 + r) * ncols + j] = acc[r] + bv;
    }
}

// ---------------- fused encoder + keys: 2-CTA cluster per batch element ----------------
__global__ void __cluster_dims__(2, 1, 1) __launch_bounds__(1024, 1) enc_fused(
    const float* __restrict__ e0_gk, const float* __restrict__ e0_ck,
    const float* __restrict__ e1_gk, const float* __restrict__ e1_gb,
    const float* __restrict__ e1_ck, const float* __restrict__ e1_cb,
    const float* __restrict__ W_mem, const int* __restrict__ x_len)
{
    int b = blockIdx.x >> 1;
    unsigned rank = ctarank_();
    unsigned peer = rank ^ 1u;
    int tid = threadIdx.x;
    int xlen = x_len[b];

    __shared__ float h0s[H], h1s[H], n0s[H], us0[H], us1[H], rh[H];
    __shared__ float cb[2 * H];
    __shared__ float pp[2048];
    __shared__ float mems[S][H];

    if (tid < H) { h0s[tid] = 0.f; h1s[tid] = 0.f; }
    cluster_sync_();

    for (int t = 0; t < S; t++) {
        bool valid = (t < xlen);
        mv16<128, 256, 128>(h0s, e0_gk + E * 256 + rank * 128, pp, tid);
        __syncthreads();
        if (tid < 128) {
            int gc = rank * 128 + tid;
            float acc = g_egx[(b * S + t) * 256 + gc];
            #pragma unroll
            for (int q = 0; q < 16; q++) acc += pp[q * 128 + tid];
            float v = sigmoid_fast(acc);
            if (rank == 0) { float rv = v * h0s[tid]; rh[tid] = rv; st_peer(&rh[tid], peer, rv); }
            else           { us0[tid] = v;            st_peer(&us0[tid], peer, v); }
        }
        cluster_sync_();
        mv16<64, 128, 128>(rh, e0_ck + E * 128 + rank * 64, pp, tid);
        __syncthreads();
        if (tid < 64) {
            int c = rank * 64 + tid;
            float acc = g_ecx[(b * S + t) * H + c];
            #pragma unroll
            for (int q = 0; q < 16; q++) acc += pp[q * 64 + tid];
            float cc = tanh_fast(acc);
            float u = us0[c];
            float n0 = u * h0s[c] + (1.f - u) * cc;
            n0s[c] = n0; st_peer(&n0s[c], peer, n0);
            cb[c] = n0;  st_peer(&cb[c], peer, n0);
        }
        if (tid < H) cb[H + tid] = h1s[tid];
        cluster_sync_();
        mv16<128, 256, 256>(cb, e1_gk + rank * 128, pp, tid);
        __syncthreads();
        if (tid < 128) {
            int gc = rank * 128 + tid;
            float acc = e1_gb[gc];
            #pragma unroll
            for (int q = 0; q < 16; q++) acc += pp[q * 128 + tid];
            float v = sigmoid_fast(acc);
            if (rank == 0) { float rv = v * h1s[tid]; cb[H + tid] = rv; st_peer(&cb[H + tid], peer, rv); }
            else           { us1[tid] = v;            st_peer(&us1[tid], peer, v); }
        }
        cluster_sync_();
        mv16<64, 128, 256>(cb, e1_ck + rank * 64, pp, tid);
        __syncthreads();
        if (tid < 64) {
            int c = rank * 64 + tid;
            float acc = e1_cb[c];
            #pragma unroll
            for (int q = 0; q < 16; q++) acc += pp[q * 64 + tid];
            float cc = tanh_fast(acc);
            float u = us1[c];
            float n1 = u * h1s[c] + (1.f - u) * cc;
            float mv;
            if (valid) {
                h1s[c] = n1; st_peer(&h1s[c], peer, n1);
                mv = n1;
            } else {
                mv = 0.f;
            }
            mems[t][c] = mv; st_peer(&mems[t][c], peer, mv);
            g_mem[(b * S + t) * H + c] = mv;
        }
        if (tid < H && valid) h0s[tid] = n0s[tid];
        cluster_sync_();
    }
    if (rank == 0 && tid < H) {
        g_h0[b * H + tid] = h0s[tid];
        g_h1[b * H + tid] = h1s[tid];
    }
    for (int idx = tid; idx < S * 64; idx += 1024) {
        int t = idx >> 6, c = idx & 63;
        int gc = (int)rank * 64 + c;
        float a0 = 0.f, a1 = 0.f, a2 = 0.f, a3 = 0.f;
        #pragma unroll 8
        for (int k = 0; k < H; k += 4) {
            a0 += mems[t][k]     * W_mem[k * H + gc];
            a1 += mems[t][k + 1] * W_mem[(k + 1) * H + gc];
            a2 += mems[t][k + 2] * W_mem[(k + 2) * H + gc];
            a3 += mems[t][k + 3] * W_mem[(k + 3) * H + gc];
        }
        g_keys[(b * S + t) * H + gc] = (a0 + a1) + (a2 + a3);
    }
}

// ---------------- fused decoder: 2-CTA cluster per batch element ----------------
__global__ void __cluster_dims__(2, 1, 1) __launch_bounds__(1024, 1) dec_fused(
    const float* __restrict__ d0_gk, const float* __restrict__ d0_ck,
    const float* __restrict__ d1_gk, const float* __restrict__ d1_gb,
    const float* __restrict__ d1_ck, const float* __restrict__ d1_cb,
    const float* __restrict__ W_q, const float* __restrict__ v_att,
    const float* __restrict__ W_attn, const int* __restrict__ x_len)
{
    int b = blockIdx.x >> 1;
    unsigned rank = ctarank_();
    unsigned peer = rank ^ 1u;
    int tid = threadIdx.x;
    int lid = tid & 31;
    int wid = tid >> 5;
    int xlen = x_len[b];

    __shared__ float h0s[H], h1s[H], n0s[H], n1s[H], qs[H], us0[H], us1[H];
    __shared__ float cb[2 * H];
    __shared__ float pp[2048];
    __shared__ float sco[S];

    if (tid < H) {
        float h0 = g_h0[b * H + tid];
        h0s[tid] = h0;
        h1s[tid] = g_h1[b * H + tid];
        cb[tid] = 0.f;
        cb[H + tid] = h0;
    }
    cluster_sync_();

    for (int t = 0; t < S; t++) {
        mv16<128, 256, 256>(cb, d0_gk + E * 256 + rank * 128, pp, tid);
        __syncthreads();
        if (tid < 128) {
            int gc = rank * 128 + tid;
            float acc = g_dgx[(b * S + t) * 256 + gc];
            #pragma unroll
            for (int q = 0; q < 16; q++) acc += pp[q * 128 + tid];
            float v = sigmoid_fast(acc);
            if (rank == 0) { float rv = v * h0s[tid]; cb[H + tid] = rv; st_peer(&cb[H + tid], peer, rv); }
            else           { us0[tid] = v;            st_peer(&us0[tid], peer, v); }
        }
        cluster_sync_();
        mv16<64, 128, 256>(cb, d0_ck + E * 128 + rank * 64, pp, tid);
        __syncthreads();
        if (tid < 64) {
            int c = rank * 64 + tid;
            float acc = g_dcx[(b * S + t) * H + c];
            #pragma unroll
            for (int q = 0; q < 16; q++) acc += pp[q * 64 + tid];
            float cc = tanh_fast(acc);
            float u = us0[c];
            float n0 = u * h0s[c] + (1.f - u) * cc;
            n0s[c] = n0; st_peer(&n0s[c], peer, n0);
            cb[c] = n0;  st_peer(&cb[c], peer, n0);
        }
        if (tid < H) cb[H + tid] = h1s[tid];
        cluster_sync_();
        mv16<128, 256, 256>(cb, d1_gk + rank * 128, pp, tid);
        __syncthreads();
        if (tid < 128) {
            int gc = rank * 128 + tid;
            float acc = d1_gb[gc];
            #pragma unroll
            for (int q = 0; q < 16; q++) acc += pp[q * 128 + tid];
            float v = sigmoid_fast(acc);
            if (rank == 0) { float rv = v * h1s[tid]; cb[H + tid] = rv; st_peer(&cb[H + tid], peer, rv); }
            else           { us1[tid] = v;            st_peer(&us1[tid], peer, v); }
        }
        cluster_sync_();
        mv16<64, 128, 256>(cb, d1_ck + rank * 64, pp, tid);
        __syncthreads();
        if (tid < 64) {
            int c = rank * 64 + tid;
            float acc = d1_cb[c];
            #pragma unroll
            for (int q = 0; q < 16; q++) acc += pp[q * 64 + tid];
            float cc = tanh_fast(acc);
            float u = us1[c];
            float n1 = u * h1s[c] + (1.f - u) * cc;
            n1s[c] = n1; st_peer(&n1s[c], peer, n1);
        }
        cluster_sync_();
        mv16<64, 128, 128>(n1s, W_q + rank * 64, pp, tid);
        __syncthreads();
        if (tid < 64) {
            int c = rank * 64 + tid;
            float acc = 0.f;
            #pragma unroll
            for (int q = 0; q < 16; q++) acc += pp[q * 64 + tid];
            qs[c] = acc; st_peer(&qs[c], peer, acc);
        }
        cluster_sync_();
        if (wid < S) {
            int s = wid;
            float acc = 0.f;
            const float* kr = &g_keys[(b * S + s) * H];
            #pragma unroll
            for (int u = 0; u < 4; u++) {
                int uu = lid + u * 32;
                acc += tanh_fast(kr[uu] + qs[uu]) * v_att[uu];
            }
            #pragma unroll
            for (int off = 16; off > 0; off >>= 1)
                acc += __shfl_xor_sync(0xffffffffu, acc, off);
            if (lid == 0)
                sco[s] = (s >= xlen) ? -3.4028235e38f : acc;
        }
        __syncthreads();
        if (tid == 0) {
            float m = -3.4028235e38f;
            #pragma unroll
            for (int s = 0; s < S; s++) m = fmaxf(m, sco[s]);
            float sum = 0.f;
            #pragma unroll
            for (int s = 0; s < S; s++) { float ev = __expf(sco[s] - m); sco[s] = ev; sum += ev; }
            float inv = __fdividef(1.f, sum);
            #pragma unroll
            for (int s = 0; s < S; s++) sco[s] *= inv;
        }
        __syncthreads();
        if (tid < H) {
            float acc = 0.f;
            #pragma unroll
            for (int s = 0; s < S; s++) acc += sco[s] * g_mem[(b * S + s) * H + tid];
            cb[H + tid] = acc;
            cb[tid] = n1s[tid];
        }
        __syncthreads();
        mv16<64, 128, 256>(cb, W_attn + rank * 64, pp, tid);
        __syncthreads();
        if (tid < 64) {
            int c = rank * 64 + tid;
            float acc = 0.f;
            #pragma unroll
            for (int q = 0; q < 16; q++) acc += pp[q * 64 + tid];
            g_na[(b * S + t) * H + c] = acc;
            cb[c] = acc; st_peer(&cb[c], peer, acc);
        }
        if (tid < H) {
            h0s[tid] = n0s[tid];
            h1s[tid] = n1s[tid];
            cb[H + tid] = n0s[tid];
        }
        cluster_sync_();
    }
}

// ---------------- projection: mma.sync bf16 split-precision GEMM ----------------
// grid (NTILES, 10), 256 threads (8 warps). Tile: M=128 x N=128, K=128.
// D = A_hi@B_hi + A_hi@B_lo + A_lo@B_hi. Warp w computes rows [w*16, +16).
// smem layout (bytes): sb @0 (512), yl @512 (256), pad to 1024,
//   As_hi @1024, As_lo @35840, Bs_hi @70656, Bs_lo @105472 (each 128x136 bf16 = 34816)
//   Ds (128x129 f32 = 66048) reuses @70656 after mainloop.
#define PROJ_SMEM 140288

__global__ __launch_bounds__(256, 1) void proj_kernel(
    const float* __restrict__ bias, const int* __restrict__ y_len,
    float* __restrict__ out)
{
    extern __shared__ char psm[];
    float* sb = reinterpret_cast<float*>(psm);
    int* yl = reinterpret_cast<int*>(psm + 512);
    unsigned short* Ah = reinterpret_cast<unsigned short*>(psm + 1024);
    unsigned short* Al = reinterpret_cast<unsigned short*>(psm + 35840);
    unsigned short* Bh = reinterpret_cast<unsigned short*>(psm + 70656);
    unsigned short* Bl = reinterpret_cast<unsigned short*>(psm + 105472);

    int tid = threadIdx.x;
    int nt = blockIdx.x;
    int bm0 = blockIdx.y * 128;
    int c0 = nt * 128;

    // ---- stage B tiles (plain [n][k] -> stride-136 smem) ----
    {
        const uint4* shh = reinterpret_cast<const uint4*>(g_Bhi + (long)nt * 16384);
        const uint4* shl = reinterpret_cast<const uint4*>(g_Blo + (long)nt * 16384);
        #pragma unroll
        for (int i = tid; i < 2048; i += 256) {
            int n = i >> 4, ch = i & 15;
            *reinterpret_cast<uint4*>(Bh + n * 136 + ch * 8) = shh[i];
            *reinterpret_cast<uint4*>(Bl + n * 136 + ch * 8) = shl[i];
        }
    }
    // ---- convert A rows -> bf16 hi/lo in smem ----
    {
        int r = tid >> 1, half = tid & 1;
        const float2* ar = reinterpret_cast<const float2*>(g_na + (long)(bm0 + r) * H) + half * 32;
        uint32_t* Ah32 = reinterpret_cast<uint32_t*>(Ah) + r * 68 + half * 32;
        uint32_t* Al32 = reinterpret_cast<uint32_t*>(Al) + r * 68 + half * 32;
        #pragma unroll
        for (int i = 0; i < 32; i++) {
            float2 v = ar[i];
            __nv_bfloat16 h0 = __float2bfloat16(v.x);
            __nv_bfloat16 h1 = __float2bfloat16(v.y);
            __nv_bfloat162 hp; hp.x = h0; hp.y = h1;
            __nv_bfloat162 lp;
            lp.x = __float2bfloat16(v.x - __bfloat162float(h0));
            lp.y = __float2bfloat16(v.y - __bfloat162float(h1));
            Ah32[i] = *reinterpret_cast<uint32_t*>(&hp);
            Al32[i] = *reinterpret_cast<uint32_t*>(&lp);
        }
    }
    if (tid < 128) sb[tid] = (c0 + tid < V) ? bias[c0 + tid] : 0.f;
    if (tid < 64) yl[tid] = y_len[tid];
    __syncthreads();

    // ---- mainloop: warp w = rows [w*16, +16), all 128 cols ----
    int w = tid >> 5, lane = tid & 31;
    int g = lane >> 2, t4 = lane & 3;
    int r0 = w * 16;

    float acc[16][4];
    #pragma unroll
    for (int nn = 0; nn < 16; nn++)
        #pragma unroll
        for (int i = 0; i < 4; i++) acc[nn][i] = 0.f;

    #pragma unroll
    for (int kk = 0; kk < 8; kk++) {
        int k0 = kk * 16;
        const unsigned short* pah = Ah + (r0 + g) * 136 + k0 + t4 * 2;
        const unsigned short* pal = Al + (r0 + g) * 136 + k0 + t4 * 2;
        uint32_t ah[4], al[4];
        ah[0] = *reinterpret_cast<const uint32_t*>(pah);
        ah[1] = *reinterpret_cast<const uint32_t*>(pah + 8 * 136);
        ah[2] = *reinterpret_cast<const uint32_t*>(pah + 8);
        ah[3] = *reinterpret_cast<const uint32_t*>(pah + 8 * 136 + 8);
        al[0] = *reinterpret_cast<const uint32_t*>(pal);
        al[1] = *reinterpret_cast<const uint32_t*>(pal + 8 * 136);
        al[2] = *reinterpret_cast<const uint32_t*>(pal + 8);
        al[3] = *reinterpret_cast<const uint32_t*>(pal + 8 * 136 + 8);
        #pragma unroll
        for (int nn = 0; nn < 16; nn++) {
            const unsigned short* pbh = Bh + (nn * 8 + g) * 136 + k0 + t4 * 2;
            const unsigned short* pbl = Bl + (nn * 8 + g) * 136 + k0 + t4 * 2;
            uint32_t bh[2], bl[2];
            bh[0] = *reinterpret_cast<const uint32_t*>(pbh);
            bh[1] = *reinterpret_cast<const uint32_t*>(pbh + 8);
            bl[0] = *reinterpret_cast<const uint32_t*>(pbl);
            bl[1] = *reinterpret_cast<const uint32_t*>(pbl + 8);
            mma16816(acc[nn], ah, bh);
            mma16816(acc[nn], ah, bl);
            mma16816(acc[nn], al, bh);
        }
    }
    __syncthreads();   // done reading B area; reuse as Ds

    // ---- stage D into smem (stride 129) ----
    float* Ds = reinterpret_cast<float*>(psm + 70656);
    #pragma unroll
    for (int nn = 0; nn < 16; nn++) {
        int cc = nn * 8 + t4 * 2;
        Ds[(r0 + g) * 129 + cc]     = acc[nn][0];
        Ds[(r0 + g) * 129 + cc + 1] = acc[nn][1];
        Ds[(r0 + g + 8) * 129 + cc]     = acc[nn][2];
        Ds[(r0 + g + 8) * 129 + cc + 1] = acc[nn][3];
    }
    __syncthreads();

    // ---- coalesced write with bias + validity mask ----
    {
        int col = tid & 127;
        int rh = tid >> 7;             // 0/1 -> rows [rh*64, +64)
        bool colok = (c0 + col < V);
        float bv = sb[col];
        for (int r = rh * 64; r < rh * 64 + 64; r++) {
            int rg = bm0 + r;
            int bb = rg / S, tt = rg - bb * S;
            bool valid = (tt < yl[bb]);
            float val = valid ? (Ds[r * 129 + col] + bv) : 0.f;
            if (colok) out[(long)rg * V + c0 + col] = val;
        }
    }
}

// ---------------- host launch ----------------
extern "C" void kernel_launch(void* const* d_in, const int* in_sizes, int n_in,
                              void* d_out, int out_size) {
    const int*   x      = (const int*)d_in[0];
    const int*   x_len  = (const int*)d_in[1];
    const int*   y      = (const int*)d_in[2];
    const int*   y_len  = (const int*)d_in[3];
    const float* emb    = (const float*)d_in[4];
    const float* e0_gk  = (const float*)d_in[5];
    const float* e0_gb  = (const float*)d_in[6];
    const float* e0_ck  = (const float*)d_in[7];
    const float* e0_cb  = (const float*)d_in[8];
    const float* e1_gk  = (const float*)d_in[9];
    const float* e1_gb  = (const float*)d_in[10];
    const float* e1_ck  = (const float*)d_in[11];
    const float* e1_cb  = (const float*)d_in[12];
    const float* d0_gk  = (const float*)d_in[13];
    const float* d0_gb  = (const float*)d_in[14];
    const float* d0_ck  = (const float*)d_in[15];
    const float* d0_cb  = (const float*)d_in[16];
    const float* d1_gk  = (const float*)d_in[17];
    const float* d1_gb  = (const float*)d_in[18];
    const float* d1_ck  = (const float*)d_in[19];
    const float* d1_cb  = (const float*)d_in[20];
    const float* W_mem  = (const float*)d_in[21];
    const float* W_q    = (const float*)d_in[22];
    const float* v_att  = (const float*)d_in[23];
    const float* W_attn = (const float*)d_in[24];
    const float* W_proj = (const float*)d_in[25];
    const float* b_proj = (const float*)d_in[26];
    float* out = (float*)d_out;

    cudaFuncSetAttribute(prepB_kernel, cudaFuncAttributeMaxDynamicSharedMemorySize, 69632);
    cudaFuncSetAttribute(proj_kernel, cudaFuncAttributeMaxDynamicSharedMemorySize, PROJ_SMEM);

    prepB_kernel<<<NTILES, 256, 69632>>>(W_proj);                                    // 1
    xpart_all_kernel<<<dim3((B * S) / 8, 4), 256>>>(
        x, y, emb, e0_gk, e0_gb, e0_ck, e0_cb, d0_gk, d0_gb, d0_ck, d0_cb);          // 2
    enc_fused<<<2 * B, 1024>>>(e0_gk, e0_ck, e1_gk, e1_gb, e1_ck, e1_cb,
                               W_mem, x_len);                                        // 3
    dec_fused<<<2 * B, 1024>>>(d0_gk, d0_ck, d1_gk, d1_gb, d1_ck, d1_cb,
                               W_q, v_att, W_attn, x_len);                           // 4 <- profiled
    proj_kernel<<<dim3(NTILES, (B * S) / 128), 256, PROJ_SMEM>>>(b_proj, y_len, out); // 5
}